// round 14
// baseline (speedup 1.0000x reference)
#include <cuda_runtime.h>
#include <cuda_fp16.h>
#include <stdint.h>
#include <math.h>

namespace fv {
constexpr int C_ = 544, CIN_ = 1088, BT_ = 1024, P4_ = 4096, P16_ = 16384, PCH_ = 34;
constexpr int KP5 = 576;

// fp32 scratch (elements)
constexpr size_t OF_F    = 0;                              // [P4][544]
constexpr size_t OF_P2   = OF_F    + (size_t)P4_*C_;
constexpr size_t OF_WPT  = OF_P2   + (size_t)P4_*PCH_;
constexpr size_t OF_PP   = OF_WPT  + (size_t)PCH_*CIN_;
constexpr size_t OF_AB   = OF_PP   + (size_t)P4_*CIN_;     // [P4][2176]
constexpr size_t OF_AG   = OF_AB   + (size_t)P4_*2176;     // [P16][544]
constexpr size_t OF_FST  = OF_AG   + (size_t)P16_*C_;      // [P4][1088]
constexpr size_t OF_ATTL = OF_FST  + (size_t)P4_*CIN_;
constexpr size_t OF_ATTS = OF_ATTL + (size_t)P16_;
constexpr size_t OF_SBN  = OF_ATTS + (size_t)P16_;         // [5][2][1088]
constexpr size_t OF_RSWF = OF_SBN  + (size_t)5*2*CIN_;     // 3328 (We | W01)
constexpr size_t OF_RSW1 = OF_RSWF + 3328;                 // 1152
constexpr size_t OF_RSW2 = OF_RSW1 + 1152;
constexpr size_t OF_RSGA = OF_RSW2 + 1152;                 // 2176
constexpr size_t OF_RSWS = OF_RSGA + 2176;                 // 640
constexpr size_t OF_S6   = OF_RSWS + 640;                  // 2176
constexpr size_t OF_T6   = OF_S6   + 2176;
constexpr size_t OF_WT2  = OF_T6   + 2176;
constexpr size_t TOT_F32 = OF_WT2 + 2176;

// fp16 row-major scratch [rows][Kpad]
constexpr size_t SZ_FB   = (size_t)P4_ * KP5;
constexpr size_t SZ_H    = (size_t)P16_ * CIN_;
constexpr size_t SZ_WF   = (size_t)3328 * KP5;   // We(2176) | W01(1152)
constexpr size_t SZ_WB   = (size_t)1152 * 1088;
constexpr size_t SZ_WGA  = (size_t)2176 * 1088;
constexpr size_t SZ_WS   = (size_t)640 * 1088;

constexpr size_t OB_FB   = 0;
constexpr size_t OB_H0   = OB_FB   + SZ_FB;
constexpr size_t OB_H1   = OB_H0   + SZ_H;
constexpr size_t OB_H2   = OB_H1   + SZ_H;
constexpr size_t OB_G    = OB_H2   + SZ_H;
constexpr size_t OB_WF   = OB_G    + SZ_H;
constexpr size_t OB_W1   = OB_WF   + SZ_WF;
constexpr size_t OB_W2   = OB_W1   + SZ_WB;
constexpr size_t OB_WGA  = OB_W2   + SZ_WB;
constexpr size_t OB_WS   = OB_WGA  + SZ_WGA;
constexpr size_t TOT_H16 = OB_WS   + SZ_WS;
}  // namespace fv

__device__ float  g_F32[fv::TOT_F32];
__device__ __half g_H16[fv::TOT_H16];

using namespace fv;

// ---------------- baseline-PTX helpers ----------------
__device__ __forceinline__ uint32_t smem_u32(const void* p) {
    uint32_t a;
    asm("{ .reg .u64 t; cvta.to.shared.u64 t, %1; cvt.u32.u64 %0, t; }" : "=r"(a) : "l"(p));
    return a;
}
__device__ __forceinline__ void cp16(uint32_t dst, const void* src) {
    asm volatile("cp.async.cg.shared.global [%0], [%1], 16;" :: "r"(dst), "l"(src));
}
#define CP_COMMIT() asm volatile("cp.async.commit_group;" ::: "memory")
#define CP_WAIT(n)  asm volatile("cp.async.wait_group %0;" :: "n"(n) : "memory")

__device__ __forceinline__ void ldsm_x4(uint32_t (&r)[4], uint32_t addr) {
    asm volatile("ldmatrix.sync.aligned.m8n8.x4.shared.b16 {%0,%1,%2,%3}, [%4];"
                 : "=r"(r[0]), "=r"(r[1]), "=r"(r[2]), "=r"(r[3]) : "r"(addr));
}
__device__ __forceinline__ void mma_f16(float (&d)[4], const uint32_t (&a)[4],
                                        const uint32_t (&b)[2]) {
    asm volatile(
        "mma.sync.aligned.m16n8k16.row.col.f32.f16.f16.f32 "
        "{%0,%1,%2,%3}, {%4,%5,%6,%7}, {%8,%9}, {%0,%1,%2,%3};"
        : "+f"(d[0]), "+f"(d[1]), "+f"(d[2]), "+f"(d[3])
        : "r"(a[0]), "r"(a[1]), "r"(a[2]), "r"(a[3]), "r"(b[0]), "r"(b[1]));
}

// ---------------- prep / elementwise ----------------
__global__ void k_bn_fold(const float* __restrict__ b0, const float* __restrict__ b1,
                          const float* __restrict__ b2, const float* __restrict__ b3,
                          const float* __restrict__ b4, float* __restrict__ sbn) {
    int idx = blockIdx.x * blockDim.x + threadIdx.x;
    if (idx >= 5 * CIN_) return;
    int w = idx / CIN_, c = idx % CIN_;
    const float* bn = w == 0 ? b0 : w == 1 ? b1 : w == 2 ? b2 : w == 3 ? b3 : b4;
    float s = bn[c] * rsqrtf(bn[3 * CIN_ + c] + 1e-5f);
    sbn[w * 2 * CIN_ + c] = s;
    sbn[w * 2 * CIN_ + CIN_ + c] = bn[CIN_ + c] - bn[2 * CIN_ + c] * s;
}

__global__ void k_wposT(const float* __restrict__ wpos, float* __restrict__ wpt) {
    int idx = blockIdx.x * blockDim.x + threadIdx.x;
    if (idx >= PCH_ * CIN_) return;
    int k = idx / CIN_, o = idx % CIN_;
    wpt[idx] = wpos[o * PCH_ + k];
}

// weight fetch modes:
// 0: srcA[r*ld + k]
// 2: stacked Wsm^T: srcA[(r/544)*295936 + k*544 + (r%544)]
// 3: stacked We:    srcA[(r%1088)*1088 + (r/1088)*544 + k]
// 5: two stacked:   r<1088 ? srcA[r*1088+k] : srcB[(r-1088)*1088+k]
__device__ __forceinline__ float wfetch(const float* srcA, const float* srcB,
                                        int ld, int mode, int r, int k) {
    if (mode == 0) return srcA[(size_t)r * ld + k];
    if (mode == 2) return srcA[(size_t)(r / 544) * 295936 + (size_t)k * 544 + (r % 544)];
    if (mode == 3) return srcA[(size_t)(r % 1088) * 1088 + (size_t)(r / 1088) * 544 + k];
    return (r < 1088) ? srcA[(size_t)r * 1088 + k] : srcB[(size_t)(r - 1088) * 1088 + k];
}

// fused per-row scale + fp16 convert; one warp per row
__global__ void k_wsp(const float* __restrict__ srcA, const float* __restrict__ srcB,
                      int ld, int Msrc, int Ksrc, int Kp, int MP, int mode,
                      float* __restrict__ rs, __half* __restrict__ dst) {
    int wid = threadIdx.x >> 5, lane = threadIdx.x & 31;
    int r = blockIdx.x * 8 + wid;
    if (r >= MP) return;
    float mx = 0.f;
    if (r < Msrc)
        for (int k = lane; k < Ksrc; k += 32)
            mx = fmaxf(mx, fabsf(wfetch(srcA, srcB, ld, mode, r, k)));
#pragma unroll
    for (int o = 16; o > 0; o >>= 1) mx = fmaxf(mx, __shfl_xor_sync(0xFFFFFFFFu, mx, o));
    int e = 0;
    if (mx > 0.f) frexpf(mx, &e);
    float rsv = exp2f((float)e);
    if (lane == 0) rs[r] = rsv;
    float inv = 1.0f / rsv;
    for (int k0 = lane * 8; k0 < Kp; k0 += 256) {
        union { __half h[8]; uint4 v; } ph;
#pragma unroll
        for (int ee = 0; ee < 8; ee++) {
            int k = k0 + ee;
            float x = (r < Msrc && k < Ksrc) ? wfetch(srcA, srcB, ld, mode, r, k) * inv : 0.f;
            ph.h[ee] = __float2half(x);
        }
        *reinterpret_cast<uint4*>(dst + (size_t)r * Kp + k0) = ph.v;
    }
}

__global__ void k_combine(const float* __restrict__ sbn, const float* __restrict__ watt_s,
                          float* __restrict__ s6, float* __restrict__ t6,
                          float* __restrict__ wt2) {
    int m = blockIdx.x * blockDim.x + threadIdx.x;
    if (m >= 2176) return;
    if (m < 1088) {
        s6[m] = sbn[6 * CIN_ + m];
        t6[m] = sbn[7 * CIN_ + m];
        wt2[m] = 0.f;
    } else {
        int c = m - 1088;
        s6[m] = sbn[8 * CIN_ + c];
        t6[m] = sbn[9 * CIN_ + c];
        wt2[m] = watt_s[c];
    }
}

__global__ void k_build_f(const float* __restrict__ x, float* __restrict__ F,
                          __half* __restrict__ fb) {
    int idx = blockIdx.x * blockDim.x + threadIdx.x;
    if (idx >= P4_ * 72) return;
    int p = idx / 72, c0 = (idx % 72) * 8;
    int bt = p >> 2, n = p & 3;
    union { __half h[8]; uint4 v; } ph;
    float vv[8];
#pragma unroll
    for (int e = 0; e < 8; e++) {
        int c = c0 + e;
        vv[e] = (c < C_) ? x[((size_t)bt * C_ + c) * 4 + n] : 0.f;
        ph.h[e] = __float2half(vv[e]);
    }
    *reinterpret_cast<uint4*>(fb + (size_t)p * KP5 + c0) = ph.v;
    if (c0 < C_) {
        float4* d = reinterpret_cast<float4*>(F + (size_t)p * C_ + c0);
        d[0] = make_float4(vv[0], vv[1], vv[2], vv[3]);
        d[1] = make_float4(vv[4], vv[5], vv[6], vv[7]);
    }
}

__global__ void k_build_p(const float* __restrict__ pos, float* __restrict__ P2) {
    int idx = blockIdx.x * blockDim.x + threadIdx.x;
    if (idx >= P4_ * PCH_) return;
    int p = idx / PCH_, k = idx % PCH_;
    P2[idx] = pos[((size_t)(p >> 2) * PCH_ + k) * 4 + (p & 3)];
}

__global__ void k_pos(const float* __restrict__ wpt, const float* __restrict__ P2,
                      float* __restrict__ PP) {
    int idx = blockIdx.x * blockDim.x + threadIdx.x;
    if (idx >= P4_ * CIN_) return;
    int p = idx / CIN_, o = idx % CIN_;
    float acc = 0.f;
#pragma unroll
    for (int k = 0; k < PCH_; k++) acc = fmaf(wpt[k * CIN_ + o], P2[p * PCH_ + k], acc);
    PP[idx] = acc;
}

__global__ void k_h0(const float* __restrict__ AB, const float* __restrict__ PP,
                     const float* __restrict__ bpos, const float* __restrict__ sbn,
                     __half* __restrict__ hh) {
    int idx = blockIdx.x * blockDim.x + threadIdx.x;
    if (idx >= P16_ * 136) return;
    int p16 = idx / 136, o0 = (idx % 136) * 8;
    int bt = p16 >> 4, ij = p16 & 15, i = ij >> 2, j = ij & 3;
    size_t pa = (size_t)(bt * 4 + i) * 2176 + o0;
    size_t pb = (size_t)(bt * 4 + j) * 2176 + 1088 + o0;
    size_t qi = (size_t)(bt * 4 + i) * CIN_ + o0;
    size_t qj = (size_t)(bt * 4 + j) * CIN_ + o0;
    union { __half h[8]; uint4 v; } ph;
#pragma unroll
    for (int e = 0; e < 8; e++) {
        int o = o0 + e;
        float v = fmaxf(fmaf(sbn[o], AB[pa + e] + AB[pb + e], sbn[CIN_ + o]), 0.f);
        v += PP[qi + e] - PP[qj + e] + bpos[o];
        ph.h[e] = __float2half(v);
    }
    *reinterpret_cast<uint4*>(hh + (size_t)p16 * CIN_ + o0) = ph.v;
}

__global__ void k_attl_init(const float* __restrict__ b, float* __restrict__ L) {
    int p = blockIdx.x * blockDim.x + threadIdx.x;
    if (p < P16_) L[p] = b[0];
}

__global__ void k_softmax(const float* __restrict__ L, float* __restrict__ S) {
    int r = blockIdx.x * blockDim.x + threadIdx.x;
    if (r >= P4_) return;
    float l0 = L[r*4], l1 = L[r*4+1], l2 = L[r*4+2], l3 = L[r*4+3];
    float m = fmaxf(fmaxf(l0, l1), fmaxf(l2, l3));
    float e0 = __expf(l0-m), e1 = __expf(l1-m), e2 = __expf(l2-m), e3 = __expf(l3-m);
    float inv = 1.f / (e0+e1+e2+e3);
    S[r*4]=e0*inv; S[r*4+1]=e1*inv; S[r*4+2]=e2*inv; S[r*4+3]=e3*inv;
}

__global__ void k_fuse(const float* __restrict__ F, const float* __restrict__ FST,
                       const float* __restrict__ AG, const float* __restrict__ S,
                       float* __restrict__ out) {
    int idx = blockIdx.x * blockDim.x + threadIdx.x;
    if (idx >= BT_ * 2176) return;
    int bt = idx / 2176, rem = idx % 2176;
    int i = rem / C_, d = rem % C_;
    int ri = bt * 4 + i;
    float acc = F[(size_t)ri * C_ + d];
#pragma unroll
    for (int j = 0; j < 4; j++) {
        float a = S[ri * 4 + j];
        if (j == i) acc = fmaf(FST[(size_t)ri * CIN_ + d], a, acc);
        else acc = fmaf(FST[(size_t)(bt*4+j) * CIN_ + 544 + d] *
                        AG[(size_t)(bt*16+i*4+j) * C_ + d], a, acc);
    }
    out[(size_t)bt * 2176 + d * 4 + i] = acc;
}

// ---------------- HMMA fp16 GEMM: 128x128 tile, 512 threads, 4x4 warps, BK=64 ----------------
// EPI: 2 relu->fp16 | 3 fp16resid+relu->fp16 | 4 v*rs+bias fp32
//      | 6 hybrid: m<1088 relu->fp16 G, m>=1088 att-dot atomicAdd
//      | 7 dual fp32: m<2176 -> outf (ld 2176), 2176<=m<3264 -> outf2 (ld 1088), else skip
constexpr int TIL = 16384;       // 128 rows x 128 B
constexpr int STG = 2 * TIL;     // 32 KB
constexpr int SMEMB = 98304;     // 3 stages

__device__ __forceinline__ uint32_t swadr(uint32_t base, int row, int c16) {
    return base + row * 128 + ((c16 ^ (row & 7)) << 4);
}

template <int EPI>
__global__ void __launch_bounds__(512, 2)
gemm_mma(const __half* __restrict__ Ag, const __half* __restrict__ Bg,
         int K, int KB, int Mreal,
         float* __restrict__ outf, int ldo,
         __half* __restrict__ oh, int ldob,
         const float* __restrict__ sv, const float* __restrict__ tv,
         const float* __restrict__ rs,
         const __half* __restrict__ r16,
         const float* __restrict__ watt,
         float* __restrict__ outf2) {
    extern __shared__ __half smbuf[];
    const uint32_t sb = smem_u32(smbuf);
    const int tid = threadIdx.x, lane = tid & 31, wid = tid >> 5;
    const int mt = blockIdx.x, nt = blockIdx.y;
    // 4x4 warp grid: warp tile 32 x 32
    const int wm = (wid & 3) * 32, wn = (wid >> 2) * 32;

    float acc[2][4][4];
#pragma unroll
    for (int a = 0; a < 2; a++)
#pragma unroll
        for (int b = 0; b < 4; b++)
#pragma unroll
            for (int c = 0; c < 4; c++) acc[a][b][c] = 0.f;

    auto load_stage = [&](int s, int kb) {
        uint32_t dstb = sb + s * STG;
        int k0 = kb * 64;
#pragma unroll
        for (int c = 0; c < 2; c++) {
            int q = tid + c * 512;
            int r = q >> 3, ch = q & 7;
            uint32_t d = dstb + r * 128 + ((ch ^ (r & 7)) << 4);
            size_t offA = (size_t)(mt * 128 + r) * K + k0 + ch * 8;
            size_t offB = (size_t)(nt * 128 + r) * K + k0 + ch * 8;
            cp16(d,       Ag + offA);
            cp16(d + TIL, Bg + offB);
        }
    };

    const int grp = lane >> 3, lrow = lane & 7;

    auto compute_stage = [&](int s) {
        uint32_t base = sb + s * STG;
#pragma unroll
        for (int ks2 = 0; ks2 < 4; ks2++) {
            uint32_t ah[2][4], bf[4][2];
            const int cA = ks2 * 2 + (grp >> 1);
            const int cB = ks2 * 2 + (grp & 1);
#pragma unroll
            for (int mi = 0; mi < 2; mi++) {
                int row = wm + mi * 16 + (grp & 1) * 8 + lrow;
                ldsm_x4(ah[mi], swadr(base, row, cA));
            }
#pragma unroll
            for (int n2 = 0; n2 < 2; n2++) {
                int row = wn + n2 * 16 + (grp >> 1) * 8 + lrow;
                uint32_t q[4];
                ldsm_x4(q, swadr(base + TIL, row, cB));
                bf[n2 * 2][0] = q[0]; bf[n2 * 2][1] = q[1];
                bf[n2 * 2 + 1][0] = q[2]; bf[n2 * 2 + 1][1] = q[3];
            }
#pragma unroll
            for (int mi = 0; mi < 2; mi++)
#pragma unroll
                for (int ni = 0; ni < 4; ni++) mma_f16(acc[mi][ni], ah[mi], bf[ni]);
        }
    };

    load_stage(0, 0); CP_COMMIT();
    if (KB > 1) { load_stage(1, 1); CP_COMMIT(); }
    for (int kb = 0; kb < KB; kb++) {
        if (kb + 1 < KB) { CP_WAIT(1); } else { CP_WAIT(0); }
        __syncthreads();
        if (kb + 2 < KB) { load_stage((kb + 2) % 3, kb + 2); CP_COMMIT(); }
        compute_stage(kb % 3);
    }
    __syncthreads();

    // transpose through smem: Cs[n (128)][m (128 + pad 4)]
    float* Cs = reinterpret_cast<float*>(smbuf);
#pragma unroll
    for (int mi = 0; mi < 2; mi++)
#pragma unroll
        for (int ni = 0; ni < 4; ni++) {
            int rm = wm + mi * 16 + (lane >> 2);
            int cn = wn + ni * 8 + 2 * (lane & 3);
            Cs[cn * 132 + rm]           = acc[mi][ni][0];
            Cs[(cn + 1) * 132 + rm]     = acc[mi][ni][1];
            Cs[cn * 132 + rm + 8]       = acc[mi][ni][2];
            Cs[(cn + 1) * 132 + rm + 8] = acc[mi][ni][3];
        }
    __syncthreads();

    {
        int nl = tid >> 2, m0 = (tid & 3) * 32;
        int ng = nt * 128 + nl;
        int mg0 = mt * 128 + m0;
        if constexpr (EPI == 6) {
            if (mg0 < 1088) {
#pragma unroll
                for (int j0 = 0; j0 < 32; j0 += 8) {
                    union { __half h[8]; uint4 v; } ph;
#pragma unroll
                    for (int e = 0; e < 8; e++) {
                        int m = mg0 + j0 + e;
                        float v = Cs[nl * 132 + m0 + j0 + e] * rs[m];
                        ph.h[e] = __float2half(fmaxf(fmaf(sv[m], v, tv[m]), 0.f));
                    }
                    *reinterpret_cast<uint4*>(oh + (size_t)ng * ldob + mg0 + j0) = ph.v;
                }
            } else {
                float wsum = 0.f;
#pragma unroll 8
                for (int j = 0; j < 32; j++) {
                    int m = mg0 + j;
                    float v = Cs[nl * 132 + m0 + j] * rs[m];
                    wsum = fmaf(fmaxf(fmaf(sv[m], v, tv[m]), 0.f), watt[m], wsum);
                }
                atomicAdd(&outf[ng], wsum);
            }
        } else if constexpr (EPI == 7) {
#pragma unroll
            for (int j0 = 0; j0 < 32; j0 += 4) {
                int m = mg0 + j0;
                if (m >= 2176 && m - 2176 >= 1088) break;   // skip W01 padding rows
                float4 ov;
                float* pv = reinterpret_cast<float*>(&ov);
#pragma unroll
                for (int e = 0; e < 4; e++)
                    pv[e] = Cs[nl * 132 + m0 + j0 + e] * rs[m + e];
                if (m < 2176)
                    *reinterpret_cast<float4*>(outf + (size_t)ng * 2176 + m) = ov;
                else
                    *reinterpret_cast<float4*>(outf2 + (size_t)ng * 1088 + m - 2176) = ov;
            }
        } else if constexpr (EPI == 2 || EPI == 3) {
#pragma unroll
            for (int j0 = 0; j0 < 32; j0 += 8) {
                if (mg0 + j0 >= Mreal) break;
                union { __half h[8]; uint4 v; } ph;
                float rv[8];
                if constexpr (EPI == 3) {
                    uint4 r4 = *reinterpret_cast<const uint4*>(r16 + (size_t)ng * ldob + mg0 + j0);
                    const __half* rr = reinterpret_cast<const __half*>(&r4);
#pragma unroll
                    for (int e = 0; e < 8; e++) rv[e] = __half2float(rr[e]);
                }
#pragma unroll
                for (int e = 0; e < 8; e++) {
                    int m = mg0 + j0 + e;
                    float v = Cs[nl * 132 + m0 + j0 + e] * rs[m];
                    float w = fmaxf(fmaf(sv[m], v, tv[m]), 0.f);
                    if constexpr (EPI == 3) w += rv[e];
                    ph.h[e] = __float2half(w);
                }
                *reinterpret_cast<uint4*>(oh + (size_t)ng * ldob + mg0 + j0) = ph.v;
            }
        } else {  // EPI 4
#pragma unroll
            for (int j0 = 0; j0 < 32; j0 += 4) {
                if (mg0 + j0 >= Mreal) break;
                float4 ov;
                float* pv = reinterpret_cast<float*>(&ov);
#pragma unroll
                for (int e = 0; e < 4; e++) {
                    int m = mg0 + j0 + e;
                    pv[e] = Cs[nl * 132 + m0 + j0 + e] * rs[m] + sv[m];
                }
                *reinterpret_cast<float4*>(outf + (size_t)ng * ldo + mg0 + j0) = ov;
            }
        }
    }
}

// ---------------- launch ----------------
extern "C" void kernel_launch(void* const* d_in, const int* in_sizes, int n_in,
                              void* d_out, int out_size) {
    const float *x = (const float*)d_in[0], *pos2d = (const float*)d_in[1];
    const float *w_pos = (const float*)d_in[2], *b_pos = (const float*)d_in[3];
    const float *w_e = (const float*)d_in[4],  *w1 = (const float*)d_in[6];
    const float *w2 = (const float*)d_in[8],   *w_ag = (const float*)d_in[10];
    const float *w_ag_s = (const float*)d_in[12], *b_ag_s = (const float*)d_in[13];
    const float *w_att = (const float*)d_in[14], *w_att_s = (const float*)d_in[16];
    const float *b_att_s = (const float*)d_in[17], *Wsm = (const float*)d_in[18];
    float* out = (float*)d_out;

    float* F32 = nullptr;  __half* H16 = nullptr;
    cudaGetSymbolAddress((void**)&F32, g_F32);
    cudaGetSymbolAddress((void**)&H16, g_H16);

    float *F = F32+OF_F, *P2 = F32+OF_P2, *WPT = F32+OF_WPT, *PP = F32+OF_PP;
    float *AB = F32+OF_AB, *AG = F32+OF_AG, *FST = F32+OF_FST;
    float *ATTL = F32+OF_ATTL, *ATTS = F32+OF_ATTS, *SBN = F32+OF_SBN;
    float *RSWF = F32+OF_RSWF, *RSW1 = F32+OF_RSW1, *RSW2 = F32+OF_RSW2;
    float *RSGA = F32+OF_RSGA, *RSWS = F32+OF_RSWS;
    float *S6 = F32+OF_S6, *T6 = F32+OF_T6, *WT2 = F32+OF_WT2;

    cudaFuncSetAttribute(gemm_mma<2>, cudaFuncAttributeMaxDynamicSharedMemorySize, SMEMB);
    cudaFuncSetAttribute(gemm_mma<3>, cudaFuncAttributeMaxDynamicSharedMemorySize, SMEMB);
    cudaFuncSetAttribute(gemm_mma<4>, cudaFuncAttributeMaxDynamicSharedMemorySize, SMEMB);
    cudaFuncSetAttribute(gemm_mma<6>, cudaFuncAttributeMaxDynamicSharedMemorySize, SMEMB);
    cudaFuncSetAttribute(gemm_mma<7>, cudaFuncAttributeMaxDynamicSharedMemorySize, SMEMB);

    // slots 1-3 prep, slot 4 = merged FB GEMM (ncu captures the 4th launch)
    k_build_f<<<(P4_*72+255)/256, 256>>>(x, F, H16+OB_FB);
    k_wsp<<<(2176+7)/8, 256>>>(w_e, nullptr, 0, 2176, 544, KP5, 2176, 3, RSWF, H16+OB_WF);
    k_wsp<<<(1152+7)/8, 256>>>(Wsm, nullptr, 0, 1088, 544, KP5, 1152, 2,
                               RSWF + 2176, H16 + OB_WF + (size_t)2176 * KP5);
    // stacked [We(2176); W01(1152)] @ f -> AB | FST
    gemm_mma<7><<<dim3(26,32),512,SMEMB>>>(H16+OB_WF, H16+OB_FB,
                                           KP5, 9, 3328, AB, 2176, nullptr, 0,
                                           nullptr, nullptr, RSWF, nullptr, nullptr, FST);

    k_bn_fold<<<(5*CIN_+255)/256, 256>>>((const float*)d_in[5], (const float*)d_in[7],
                                         (const float*)d_in[9], (const float*)d_in[11],
                                         (const float*)d_in[15], SBN);
    k_wposT<<<(PCH_*CIN_+255)/256, 256>>>(w_pos, WPT);
    k_build_p<<<(P4_*PCH_+255)/256, 256>>>(pos2d, P2);
    k_pos<<<(P4_*CIN_+255)/256, 256>>>(WPT, P2, PP);
    k_h0<<<(P16_*136+255)/256, 256>>>(AB, PP, b_pos, SBN, H16+OB_H0);

    // weight preps
    k_wsp<<<(1152+7)/8, 256>>>(w1,    nullptr, CIN_, 1088, 1088, 1088, 1152, 0, RSW1, H16+OB_W1);
    k_wsp<<<(1152+7)/8, 256>>>(w2,    nullptr, CIN_, 1088, 1088, 1088, 1152, 0, RSW2, H16+OB_W2);
    k_wsp<<<(2176+7)/8, 256>>>(w_ag,  w_att,   CIN_, 2176, 1088, 1088, 2176, 5, RSGA, H16+OB_WGA);
    k_wsp<<<(640+7)/8, 256>>>(w_ag_s, nullptr, CIN_, 544, 1088, 1088, 640, 0, RSWS, H16+OB_WS);
    k_combine<<<(2176+255)/256, 256>>>(SBN, w_att_s, S6, T6, WT2);

    // trunk
    gemm_mma<2><<<dim3(9,128),512,SMEMB>>>(H16+OB_W1, H16+OB_H0,
                                           1088, 17, 1088, nullptr, 0, H16+OB_H1, CIN_,
                                           SBN+2*CIN_, SBN+3*CIN_, RSW1, nullptr, nullptr, nullptr);
    gemm_mma<3><<<dim3(9,128),512,SMEMB>>>(H16+OB_W2, H16+OB_H1,
                                           1088, 17, 1088, nullptr, 0, H16+OB_H2, CIN_,
                                           SBN+4*CIN_, SBN+5*CIN_, RSW2, H16+OB_H0, nullptr, nullptr);
    // merged ag+att stacked GEMM (hybrid epilogue)
    k_attl_init<<<(P16_+255)/256, 256>>>(b_att_s, ATTL);
    gemm_mma<6><<<dim3(17,128),512,SMEMB>>>(H16+OB_WGA, H16+OB_H2,
                                            1088, 17, 2176, ATTL, 0, H16+OB_G, CIN_,
                                            S6, T6, RSGA, nullptr, WT2, nullptr);
    gemm_mma<4><<<dim3(5,128),512,SMEMB>>>(H16+OB_WS, H16+OB_G,
                                           1088, 17, 544, AG, C_, nullptr, 0,
                                           b_ag_s, nullptr, RSWS, nullptr, nullptr, nullptr);
    k_softmax<<<(P4_+255)/256, 256>>>(ATTL, ATTS);

    k_fuse<<<(BT_*2176+255)/256, 256>>>(F, FST, AG, ATTS, out);
}

// round 15
// speedup vs baseline: 1.1233x; 1.1233x over previous
#include <cuda_runtime.h>
#include <cuda_fp16.h>
#include <stdint.h>
#include <math.h>

namespace fv {
constexpr int C_ = 544, CIN_ = 1088, BT_ = 1024, P4_ = 4096, P16_ = 16384, PCH_ = 34;
constexpr int KP5 = 576;

// fp32 scratch (elements)
constexpr size_t OF_F    = 0;                              // [P4][544]
constexpr size_t OF_P2   = OF_F    + (size_t)P4_*C_;       // [P4][34]
constexpr size_t OF_PP   = OF_P2   + (size_t)P4_*PCH_;     // [P4][1088]
constexpr size_t OF_AB   = OF_PP   + (size_t)P4_*CIN_;     // [P4][2176]
constexpr size_t OF_AG   = OF_AB   + (size_t)P4_*2176;     // [P16][544]
constexpr size_t OF_FST  = OF_AG   + (size_t)P16_*C_;      // [P4][1088]
constexpr size_t OF_ATTL = OF_FST  + (size_t)P4_*CIN_;
constexpr size_t OF_ATTS = OF_ATTL + (size_t)P16_;
constexpr size_t OF_SBN  = OF_ATTS + (size_t)P16_;         // [5][2][1088]
constexpr size_t OF_RSWF = OF_SBN  + (size_t)5*2*CIN_;     // 3328
constexpr size_t OF_RSW1 = OF_RSWF + 3328;
constexpr size_t OF_RSW2 = OF_RSW1 + 1152;
constexpr size_t OF_RSGA = OF_RSW2 + 1152;                 // 2176
constexpr size_t OF_RSWS = OF_RSGA + 2176;                 // 640
constexpr size_t OF_S6   = OF_RSWS + 640;                  // 2176
constexpr size_t OF_T6   = OF_S6   + 2176;
constexpr size_t OF_WT2  = OF_T6   + 2176;
constexpr size_t TOT_F32 = OF_WT2 + 2176;

// fp16 row-major scratch [rows][Kpad]
constexpr size_t SZ_FB   = (size_t)P4_ * KP5;
constexpr size_t SZ_H    = (size_t)P16_ * CIN_;
constexpr size_t SZ_WF   = (size_t)3328 * KP5;   // We(2176) | W01(1088) | pad(64)
constexpr size_t SZ_WB   = (size_t)1152 * 1088;
constexpr size_t SZ_WGA  = (size_t)2176 * 1088;
constexpr size_t SZ_WS   = (size_t)640 * 1088;

constexpr size_t OB_FB   = 0;
constexpr size_t OB_H0   = OB_FB   + SZ_FB;
constexpr size_t OB_H1   = OB_H0   + SZ_H;
constexpr size_t OB_H2   = OB_H1   + SZ_H;
constexpr size_t OB_G    = OB_H2   + SZ_H;
constexpr size_t OB_WF   = OB_G    + SZ_H;
constexpr size_t OB_W1   = OB_WF   + SZ_WF;
constexpr size_t OB_W2   = OB_W1   + SZ_WB;
constexpr size_t OB_WGA  = OB_W2   + SZ_WB;
constexpr size_t OB_WS   = OB_WGA  + SZ_WGA;
constexpr size_t TOT_H16 = OB_WS   + SZ_WS;

// mega-prep block ranges (256-thread blocks)
constexpr int PB_BF   = 1152;                 // build_f
constexpr int PB_WE   = PB_BF + 272;          // wsp We (mode 3, MP 2176)
constexpr int PB_W01  = PB_WE + 144;          // wsp Wsm^T (mode 2, MP 1152)
constexpr int PB_W1   = PB_W01 + 144;
constexpr int PB_W2   = PB_W1 + 144;
constexpr int PB_WGA  = PB_W2 + 272;          // wsp ag|att (mode 5, MP 2176)
constexpr int PB_WS   = PB_WGA + 80;          // wsp ag_s (MP 640)
constexpr int PB_BN   = PB_WS + 22;           // bn_fold
constexpr int PB_BP   = PB_BN + 545;          // build_p
constexpr int PB_AI   = PB_BP + 64;           // attl_init
constexpr int PB_CM   = PB_AI + 9;            // combine
constexpr int PB_TOT  = PB_CM;
}  // namespace fv

__device__ float  g_F32[fv::TOT_F32];
__device__ __half g_H16[fv::TOT_H16];

using namespace fv;

// ---------------- baseline-PTX helpers ----------------
__device__ __forceinline__ uint32_t smem_u32(const void* p) {
    uint32_t a;
    asm("{ .reg .u64 t; cvta.to.shared.u64 t, %1; cvt.u32.u64 %0, t; }" : "=r"(a) : "l"(p));
    return a;
}
__device__ __forceinline__ void cp16(uint32_t dst, const void* src) {
    asm volatile("cp.async.cg.shared.global [%0], [%1], 16;" :: "r"(dst), "l"(src));
}
#define CP_COMMIT() asm volatile("cp.async.commit_group;" ::: "memory")
#define CP_WAIT(n)  asm volatile("cp.async.wait_group %0;" :: "n"(n) : "memory")

__device__ __forceinline__ void ldsm_x4(uint32_t (&r)[4], uint32_t addr) {
    asm volatile("ldmatrix.sync.aligned.m8n8.x4.shared.b16 {%0,%1,%2,%3}, [%4];"
                 : "=r"(r[0]), "=r"(r[1]), "=r"(r[2]), "=r"(r[3]) : "r"(addr));
}
__device__ __forceinline__ void mma_f16(float (&d)[4], const uint32_t (&a)[4],
                                        const uint32_t (&b)[2]) {
    asm volatile(
        "mma.sync.aligned.m16n8k16.row.col.f32.f16.f16.f32 "
        "{%0,%1,%2,%3}, {%4,%5,%6,%7}, {%8,%9}, {%0,%1,%2,%3};"
        : "+f"(d[0]), "+f"(d[1]), "+f"(d[2]), "+f"(d[3])
        : "r"(a[0]), "r"(a[1]), "r"(a[2]), "r"(a[3]), "r"(b[0]), "r"(b[1]));
}

// weight fetch modes:
// 0: srcA[r*ld + k]
// 2: stacked Wsm^T: srcA[(r/544)*295936 + k*544 + (r%544)]
// 3: stacked We:    srcA[(r%1088)*1088 + (r/1088)*544 + k]
// 5: two stacked:   r<1088 ? srcA[r*1088+k] : srcB[(r-1088)*1088+k]
__device__ __forceinline__ float wfetch(const float* srcA, const float* srcB,
                                        int ld, int mode, int r, int k) {
    if (mode == 0) return srcA[(size_t)r * ld + k];
    if (mode == 2) return srcA[(size_t)(r / 544) * 295936 + (size_t)k * 544 + (r % 544)];
    if (mode == 3) return srcA[(size_t)(r % 1088) * 1088 + (size_t)(r / 1088) * 544 + k];
    return (r < 1088) ? srcA[(size_t)r * 1088 + k] : srcB[(size_t)(r - 1088) * 1088 + k];
}

// per-row scale + fp16 convert; one warp per row, 8 rows per block
__device__ __forceinline__ void dev_wsp(int lb, const float* srcA, const float* srcB,
                                        int ld, int Msrc, int Ksrc, int Kp, int MP, int mode,
                                        float* rs, __half* dst) {
    int wid = threadIdx.x >> 5, lane = threadIdx.x & 31;
    int r = lb * 8 + wid;
    if (r >= MP) return;
    float mx = 0.f;
    if (r < Msrc)
        for (int k = lane; k < Ksrc; k += 32)
            mx = fmaxf(mx, fabsf(wfetch(srcA, srcB, ld, mode, r, k)));
#pragma unroll
    for (int o = 16; o > 0; o >>= 1) mx = fmaxf(mx, __shfl_xor_sync(0xFFFFFFFFu, mx, o));
    int e = 0;
    if (mx > 0.f) frexpf(mx, &e);
    float rsv = exp2f((float)e);
    if (lane == 0) rs[r] = rsv;
    float inv = 1.0f / rsv;
    for (int k0 = lane * 8; k0 < Kp; k0 += 256) {
        union { __half h[8]; uint4 v; } ph;
#pragma unroll
        for (int ee = 0; ee < 8; ee++) {
            int k = k0 + ee;
            float x = (r < Msrc && k < Ksrc) ? wfetch(srcA, srcB, ld, mode, r, k) * inv : 0.f;
            ph.h[ee] = __float2half(x);
        }
        *reinterpret_cast<uint4*>(dst + (size_t)r * Kp + k0) = ph.v;
    }
}

// ---------------- mega prep kernel ----------------
__global__ void k_prep(const float* __restrict__ x, const float* __restrict__ pos2d,
                       const float* __restrict__ w_e, const float* __restrict__ Wsm,
                       const float* __restrict__ w1, const float* __restrict__ w2,
                       const float* __restrict__ w_ag, const float* __restrict__ w_att,
                       const float* __restrict__ w_ag_s,
                       const float* __restrict__ b0, const float* __restrict__ b1,
                       const float* __restrict__ b2, const float* __restrict__ b3,
                       const float* __restrict__ b4,
                       const float* __restrict__ w_att_s, const float* __restrict__ b_att_s,
                       float* __restrict__ F, __half* __restrict__ FB,
                       float* __restrict__ P2, float* __restrict__ SBN,
                       float* __restrict__ RSWF, float* __restrict__ RSW1,
                       float* __restrict__ RSW2, float* __restrict__ RSGA,
                       float* __restrict__ RSWS,
                       __half* __restrict__ WF, __half* __restrict__ W1d,
                       __half* __restrict__ W2d, __half* __restrict__ WGA,
                       __half* __restrict__ WS,
                       float* __restrict__ S6, float* __restrict__ T6,
                       float* __restrict__ WT2, float* __restrict__ ATTL) {
    int b = blockIdx.x, t = threadIdx.x;
    if (b < PB_BF) {
        int idx = b * 256 + t;
        int p = idx / 72, c0 = (idx % 72) * 8;
        int bt = p >> 2, n = p & 3;
        union { __half h[8]; uint4 v; } ph;
        float vv[8];
#pragma unroll
        for (int e = 0; e < 8; e++) {
            int c = c0 + e;
            vv[e] = (c < C_) ? x[((size_t)bt * C_ + c) * 4 + n] : 0.f;
            ph.h[e] = __float2half(vv[e]);
        }
        *reinterpret_cast<uint4*>(FB + (size_t)p * KP5 + c0) = ph.v;
        if (c0 < C_) {
            float4* d = reinterpret_cast<float4*>(F + (size_t)p * C_ + c0);
            d[0] = make_float4(vv[0], vv[1], vv[2], vv[3]);
            d[1] = make_float4(vv[4], vv[5], vv[6], vv[7]);
        }
    } else if (b < PB_WE) {
        dev_wsp(b - PB_BF, w_e, nullptr, 0, 2176, 544, KP5, 2176, 3, RSWF, WF);
    } else if (b < PB_W01) {
        dev_wsp(b - PB_WE, Wsm, nullptr, 0, 1088, 544, KP5, 1152, 2,
                RSWF + 2176, WF + (size_t)2176 * KP5);
    } else if (b < PB_W1) {
        dev_wsp(b - PB_W01, w1, nullptr, CIN_, 1088, 1088, 1088, 1152, 0, RSW1, W1d);
    } else if (b < PB_W2) {
        dev_wsp(b - PB_W1, w2, nullptr, CIN_, 1088, 1088, 1088, 1152, 0, RSW2, W2d);
    } else if (b < PB_WGA) {
        dev_wsp(b - PB_W2, w_ag, w_att, CIN_, 2176, 1088, 1088, 2176, 5, RSGA, WGA);
    } else if (b < PB_WS) {
        dev_wsp(b - PB_WGA, w_ag_s, nullptr, CIN_, 544, 1088, 1088, 640, 0, RSWS, WS);
    } else if (b < PB_BN) {
        int idx = (b - PB_WS) * 256 + t;
        if (idx < 5 * CIN_) {
            int w = idx / CIN_, c = idx % CIN_;
            const float* bn = w == 0 ? b0 : w == 1 ? b1 : w == 2 ? b2 : w == 3 ? b3 : b4;
            float s = bn[c] * rsqrtf(bn[3 * CIN_ + c] + 1e-5f);
            SBN[w * 2 * CIN_ + c] = s;
            SBN[w * 2 * CIN_ + CIN_ + c] = bn[CIN_ + c] - bn[2 * CIN_ + c] * s;
        }
    } else if (b < PB_BP) {
        int idx = (b - PB_BN) * 256 + t;
        if (idx < P4_ * PCH_) {
            int p = idx / PCH_, k = idx % PCH_;
            P2[idx] = pos2d[((size_t)(p >> 2) * PCH_ + k) * 4 + (p & 3)];
        }
    } else if (b < PB_AI) {
        int p = (b - PB_BP) * 256 + t;
        if (p < P16_) ATTL[p] = b_att_s[0];
    } else {
        int m = (b - PB_AI) * 256 + t;
        if (m < 2176) {
            const float* bn = (m < 1088) ? b3 : b4;
            int c = (m < 1088) ? m : m - 1088;
            float s = bn[c] * rsqrtf(bn[3 * CIN_ + c] + 1e-5f);
            S6[m] = s;
            T6[m] = bn[CIN_ + c] - bn[2 * CIN_ + c] * s;
            WT2[m] = (m < 1088) ? 0.f : w_att_s[c];
        }
    }
}

// ---------------- remaining elementwise ----------------
__global__ void k_pos(const float* __restrict__ wpos, const float* __restrict__ P2,
                      float* __restrict__ PP) {
    int idx = blockIdx.x * blockDim.x + threadIdx.x;
    if (idx >= P4_ * CIN_) return;
    int p = idx / CIN_, o = idx % CIN_;
    float acc = 0.f;
#pragma unroll
    for (int k = 0; k < PCH_; k++) acc = fmaf(wpos[o * PCH_ + k], P2[p * PCH_ + k], acc);
    PP[idx] = acc;
}

__global__ void k_h0(const float* __restrict__ AB, const float* __restrict__ PP,
                     const float* __restrict__ bpos, const float* __restrict__ sbn,
                     __half* __restrict__ hh) {
    int idx = blockIdx.x * blockDim.x + threadIdx.x;
    if (idx >= P16_ * 136) return;
    int p16 = idx / 136, o0 = (idx % 136) * 8;
    int bt = p16 >> 4, ij = p16 & 15, i = ij >> 2, j = ij & 3;
    size_t pa = (size_t)(bt * 4 + i) * 2176 + o0;
    size_t pb = (size_t)(bt * 4 + j) * 2176 + 1088 + o0;
    size_t qi = (size_t)(bt * 4 + i) * CIN_ + o0;
    size_t qj = (size_t)(bt * 4 + j) * CIN_ + o0;
    union { __half h[8]; uint4 v; } ph;
#pragma unroll
    for (int e = 0; e < 8; e++) {
        int o = o0 + e;
        float v = fmaxf(fmaf(sbn[o], AB[pa + e] + AB[pb + e], sbn[CIN_ + o]), 0.f);
        v += PP[qi + e] - PP[qj + e] + bpos[o];
        ph.h[e] = __float2half(v);
    }
    *reinterpret_cast<uint4*>(hh + (size_t)p16 * CIN_ + o0) = ph.v;
}

__global__ void k_softmax(const float* __restrict__ L, float* __restrict__ S) {
    int r = blockIdx.x * blockDim.x + threadIdx.x;
    if (r >= P4_) return;
    float l0 = L[r*4], l1 = L[r*4+1], l2 = L[r*4+2], l3 = L[r*4+3];
    float m = fmaxf(fmaxf(l0, l1), fmaxf(l2, l3));
    float e0 = __expf(l0-m), e1 = __expf(l1-m), e2 = __expf(l2-m), e3 = __expf(l3-m);
    float inv = 1.f / (e0+e1+e2+e3);
    S[r*4]=e0*inv; S[r*4+1]=e1*inv; S[r*4+2]=e2*inv; S[r*4+3]=e3*inv;
}

__global__ void k_fuse(const float* __restrict__ F, const float* __restrict__ FST,
                       const float* __restrict__ AG, const float* __restrict__ S,
                       float* __restrict__ out) {
    int idx = blockIdx.x * blockDim.x + threadIdx.x;
    if (idx >= BT_ * 2176) return;
    int bt = idx / 2176, rem = idx % 2176;
    int i = rem / C_, d = rem % C_;
    int ri = bt * 4 + i;
    float acc = F[(size_t)ri * C_ + d];
#pragma unroll
    for (int j = 0; j < 4; j++) {
        float a = S[ri * 4 + j];
        if (j == i) acc = fmaf(FST[(size_t)ri * CIN_ + d], a, acc);
        else acc = fmaf(FST[(size_t)(bt*4+j) * CIN_ + 544 + d] *
                        AG[(size_t)(bt*16+i*4+j) * C_ + d], a, acc);
    }
    out[(size_t)bt * 2176 + d * 4 + i] = acc;
}

// ---------------- HMMA fp16 GEMM (R12 engine): 128x128 tile, 256 thr, 4x2 warps, BK=64 ----------------
// EPI: 2 relu->fp16 | 3 fp16resid+relu->fp16 | 4 v*rs+bias fp32
//      | 6 hybrid: m<1088 relu->fp16 G, m>=1088 att-dot atomicAdd
//      | 7 dual fp32: m<2176 -> outf (ld 2176), 2176<=m<3264 -> outf2 (ld 1088), else skip
constexpr int TIL = 16384;       // 128 rows x 128 B
constexpr int STG = 2 * TIL;     // 32 KB
constexpr int SMEMB = 98304;     // 3 stages (Cs 128x132 f32 aliases)

__device__ __forceinline__ uint32_t swadr(uint32_t base, int row, int c16) {
    return base + row * 128 + ((c16 ^ (row & 7)) << 4);
}

template <int EPI>
__global__ void __launch_bounds__(256, 2)
gemm_mma(const __half* __restrict__ Ag, const __half* __restrict__ Bg,
         int K, int KB, int Mreal,
         float* __restrict__ outf, int ldo,
         __half* __restrict__ oh, int ldob,
         const float* __restrict__ sv, const float* __restrict__ tv,
         const float* __restrict__ rs,
         const __half* __restrict__ r16,
         const float* __restrict__ watt,
         float* __restrict__ outf2) {
    extern __shared__ __half smbuf[];
    const uint32_t sb = smem_u32(smbuf);
    const int tid = threadIdx.x, lane = tid & 31, wid = tid >> 5;
    const int mt = blockIdx.x, nt = blockIdx.y;
    const int wm = (wid & 3) * 32, wn = (wid >> 2) * 64;

    float acc[2][8][4];
#pragma unroll
    for (int a = 0; a < 2; a++)
#pragma unroll
        for (int b = 0; b < 8; b++)
#pragma unroll
            for (int c = 0; c < 4; c++) acc[a][b][c] = 0.f;

    auto load_stage = [&](int s, int kb) {
        uint32_t dstb = sb + s * STG;
        int k0 = kb * 64;
#pragma unroll
        for (int c = 0; c < 4; c++) {
            int q = tid + c * 256;
            int r = q >> 3, ch = q & 7;
            uint32_t d = dstb + r * 128 + ((ch ^ (r & 7)) << 4);
            size_t offA = (size_t)(mt * 128 + r) * K + k0 + ch * 8;
            size_t offB = (size_t)(nt * 128 + r) * K + k0 + ch * 8;
            cp16(d,       Ag + offA);
            cp16(d + TIL, Bg + offB);
        }
    };

    const int grp = lane >> 3, lrow = lane & 7;

    auto compute_stage = [&](int s) {
        uint32_t base = sb + s * STG;
#pragma unroll
        for (int ks2 = 0; ks2 < 4; ks2++) {
            uint32_t ah[2][4], bf[8][2];
            const int cA = ks2 * 2 + (grp >> 1);
            const int cB = ks2 * 2 + (grp & 1);
#pragma unroll
            for (int mi = 0; mi < 2; mi++) {
                int row = wm + mi * 16 + (grp & 1) * 8 + lrow;
                ldsm_x4(ah[mi], swadr(base, row, cA));
            }
#pragma unroll
            for (int n2 = 0; n2 < 4; n2++) {
                int row = wn + n2 * 16 + (grp >> 1) * 8 + lrow;
                uint32_t q[4];
                ldsm_x4(q, swadr(base + TIL, row, cB));
                bf[n2 * 2][0] = q[0]; bf[n2 * 2][1] = q[1];
                bf[n2 * 2 + 1][0] = q[2]; bf[n2 * 2 + 1][1] = q[3];
            }
#pragma unroll
            for (int mi = 0; mi < 2; mi++)
#pragma unroll
                for (int ni = 0; ni < 8; ni++) mma_f16(acc[mi][ni], ah[mi], bf[ni]);
        }
    };

    load_stage(0, 0); CP_COMMIT();
    if (KB > 1) { load_stage(1, 1); CP_COMMIT(); }
    for (int kb = 0; kb < KB; kb++) {
        if (kb + 1 < KB) { CP_WAIT(1); } else { CP_WAIT(0); }
        __syncthreads();
        if (kb + 2 < KB) { load_stage((kb + 2) % 3, kb + 2); CP_COMMIT(); }
        compute_stage(kb % 3);
    }
    __syncthreads();

    // transpose through smem: Cs[n (128)][m (128 + pad 4)]
    float* Cs = reinterpret_cast<float*>(smbuf);
#pragma unroll
    for (int mi = 0; mi < 2; mi++)
#pragma unroll
        for (int ni = 0; ni < 8; ni++) {
            int rm = wm + mi * 16 + (lane >> 2);
            int cn = wn + ni * 8 + 2 * (lane & 3);
            Cs[cn * 132 + rm]           = acc[mi][ni][0];
            Cs[(cn + 1) * 132 + rm]     = acc[mi][ni][1];
            Cs[cn * 132 + rm + 8]       = acc[mi][ni][2];
            Cs[(cn + 1) * 132 + rm + 8] = acc[mi][ni][3];
        }
    __syncthreads();

    {
        int nl = tid >> 1, m0 = (tid & 1) * 64;
        int ng = nt * 128 + nl;
        int mg0 = mt * 128 + m0;
        if constexpr (EPI == 6) {
            if (mg0 < 1088) {
#pragma unroll
                for (int j0 = 0; j0 < 64; j0 += 8) {
                    union { __half h[8]; uint4 v; } ph;
#pragma unroll
                    for (int e = 0; e < 8; e++) {
                        int m = mg0 + j0 + e;
                        float v = Cs[nl * 132 + m0 + j0 + e] * rs[m];
                        ph.h[e] = __float2half(fmaxf(fmaf(sv[m], v, tv[m]), 0.f));
                    }
                    *reinterpret_cast<uint4*>(oh + (size_t)ng * ldob + mg0 + j0) = ph.v;
                }
            } else {
                float wsum = 0.f;
#pragma unroll 8
                for (int j = 0; j < 64; j++) {
                    int m = mg0 + j;
                    float v = Cs[nl * 132 + m0 + j] * rs[m];
                    wsum = fmaf(fmaxf(fmaf(sv[m], v, tv[m]), 0.f), watt[m], wsum);
                }
                atomicAdd(&outf[ng], wsum);
            }
        } else if constexpr (EPI == 7) {
#pragma unroll
            for (int j0 = 0; j0 < 64; j0 += 4) {
                int m = mg0 + j0;
                if (m >= 3264) break;   // skip W01 padding rows
                float4 ov;
                float* pv = reinterpret_cast<float*>(&ov);
#pragma unroll
                for (int e = 0; e < 4; e++)
                    pv[e] = Cs[nl * 132 + m0 + j0 + e] * rs[m + e];
                if (m < 2176)
                    *reinterpret_cast<float4*>(outf + (size_t)ng * 2176 + m) = ov;
                else
                    *reinterpret_cast<float4*>(outf2 + (size_t)ng * 1088 + m - 2176) = ov;
            }
        } else if constexpr (EPI == 2 || EPI == 3) {
#pragma unroll
            for (int j0 = 0; j0 < 64; j0 += 8) {
                if (mg0 + j0 >= Mreal) break;
                union { __half h[8]; uint4 v; } ph;
                float rv[8];
                if constexpr (EPI == 3) {
                    uint4 r4 = *reinterpret_cast<const uint4*>(r16 + (size_t)ng * ldob + mg0 + j0);
                    const __half* rr = reinterpret_cast<const __half*>(&r4);
#pragma unroll
                    for (int e = 0; e < 8; e++) rv[e] = __half2float(rr[e]);
                }
#pragma unroll
                for (int e = 0; e < 8; e++) {
                    int m = mg0 + j0 + e;
                    float v = Cs[nl * 132 + m0 + j0 + e] * rs[m];
                    float w = fmaxf(fmaf(sv[m], v, tv[m]), 0.f);
                    if constexpr (EPI == 3) w += rv[e];
                    ph.h[e] = __float2half(w);
                }
                *reinterpret_cast<uint4*>(oh + (size_t)ng * ldob + mg0 + j0) = ph.v;
            }
        } else {  // EPI 4
#pragma unroll
            for (int j0 = 0; j0 < 64; j0 += 4) {
                if (mg0 + j0 >= Mreal) break;
                float4 ov;
                float* pv = reinterpret_cast<float*>(&ov);
#pragma unroll
                for (int e = 0; e < 4; e++) {
                    int m = mg0 + j0 + e;
                    pv[e] = Cs[nl * 132 + m0 + j0 + e] * rs[m] + sv[m];
                }
                *reinterpret_cast<float4*>(outf + (size_t)ng * ldo + mg0 + j0) = ov;
            }
        }
    }
}

// ---------------- launch ----------------
extern "C" void kernel_launch(void* const* d_in, const int* in_sizes, int n_in,
                              void* d_out, int out_size) {
    const float *x = (const float*)d_in[0], *pos2d = (const float*)d_in[1];
    const float *w_pos = (const float*)d_in[2], *b_pos = (const float*)d_in[3];
    const float *w_e = (const float*)d_in[4],  *w1 = (const float*)d_in[6];
    const float *w2 = (const float*)d_in[8],   *w_ag = (const float*)d_in[10];
    const float *w_ag_s = (const float*)d_in[12], *b_ag_s = (const float*)d_in[13];
    const float *w_att = (const float*)d_in[14], *w_att_s = (const float*)d_in[16];
    const float *b_att_s = (const float*)d_in[17], *Wsm = (const float*)d_in[18];
    float* out = (float*)d_out;

    float* F32 = nullptr;  __half* H16 = nullptr;
    cudaGetSymbolAddress((void**)&F32, g_F32);
    cudaGetSymbolAddress((void**)&H16, g_H16);

    float *F = F32+OF_F, *P2 = F32+OF_P2, *PP = F32+OF_PP;
    float *AB = F32+OF_AB, *AG = F32+OF_AG, *FST = F32+OF_FST;
    float *ATTL = F32+OF_ATTL, *ATTS = F32+OF_ATTS, *SBN = F32+OF_SBN;
    float *RSWF = F32+OF_RSWF, *RSW1 = F32+OF_RSW1, *RSW2 = F32+OF_RSW2;
    float *RSGA = F32+OF_RSGA, *RSWS = F32+OF_RSWS;
    float *S6 = F32+OF_S6, *T6 = F32+OF_T6, *WT2 = F32+OF_WT2;

    cudaFuncSetAttribute(gemm_mma<2>, cudaFuncAttributeMaxDynamicSharedMemorySize, SMEMB);
    cudaFuncSetAttribute(gemm_mma<3>, cudaFuncAttributeMaxDynamicSharedMemorySize, SMEMB);
    cudaFuncSetAttribute(gemm_mma<4>, cudaFuncAttributeMaxDynamicSharedMemorySize, SMEMB);
    cudaFuncSetAttribute(gemm_mma<6>, cudaFuncAttributeMaxDynamicSharedMemorySize, SMEMB);
    cudaFuncSetAttribute(gemm_mma<7>, cudaFuncAttributeMaxDynamicSharedMemorySize, SMEMB);

    // 1: mega prep (everything input-only)
    k_prep<<<PB_TOT, 256>>>(x, pos2d, w_e, Wsm, w1, w2, w_ag, w_att, w_ag_s,
                            (const float*)d_in[5], (const float*)d_in[7],
                            (const float*)d_in[9], (const float*)d_in[11],
                            (const float*)d_in[15], w_att_s, b_att_s,
                            F, H16+OB_FB, P2, SBN, RSWF, RSW1, RSW2, RSGA, RSWS,
                            H16+OB_WF, H16+OB_W1, H16+OB_W2, H16+OB_WGA, H16+OB_WS,
                            S6, T6, WT2, ATTL);

    // 2: stacked [We(2176); W01(1088)] @ f -> AB | FST
    gemm_mma<7><<<dim3(26,32),256,SMEMB>>>(H16+OB_WF, H16+OB_FB,
                                           KP5, 9, 3328, AB, 2176, nullptr, 0,
                                           nullptr, nullptr, RSWF, nullptr, nullptr, FST);
    // 3-4: pos emb + h0 assembly
    k_pos<<<(P4_*CIN_+255)/256, 256>>>(w_pos, P2, PP);
    k_h0<<<(P16_*136+255)/256, 256>>>(AB, PP, b_pos, SBN, H16+OB_H0);

    // 5-6: trunk
    gemm_mma<2><<<dim3(9,128),256,SMEMB>>>(H16+OB_W1, H16+OB_H0,
                                           1088, 17, 1088, nullptr, 0, H16+OB_H1, CIN_,
                                           SBN+2*CIN_, SBN+3*CIN_, RSW1, nullptr, nullptr, nullptr);
    gemm_mma<3><<<dim3(9,128),256,SMEMB>>>(H16+OB_W2, H16+OB_H1,
                                           1088, 17, 1088, nullptr, 0, H16+OB_H2, CIN_,
                                           SBN+4*CIN_, SBN+5*CIN_, RSW2, H16+OB_H0, nullptr, nullptr);
    // 7: merged ag+att stacked GEMM (hybrid epilogue; ATTL pre-seeded in prep)
    gemm_mma<6><<<dim3(17,128),256,SMEMB>>>(H16+OB_WGA, H16+OB_H2,
                                            1088, 17, 2176, ATTL, 0, H16+OB_G, CIN_,
                                            S6, T6, RSGA, nullptr, WT2, nullptr);
    // 8: ag_s
    gemm_mma<4><<<dim3(5,128),256,SMEMB>>>(H16+OB_WS, H16+OB_G,
                                           1088, 17, 544, AG, C_, nullptr, 0,
                                           b_ag_s, nullptr, RSWS, nullptr, nullptr, nullptr);
    // 9-10: softmax + fuse
    k_softmax<<<(P4_+255)/256, 256>>>(ATTL, ATTS);
    k_fuse<<<(BT_*2176+255)/256, 256>>>(F, FST, AG, ATTS, out);
}

// round 16
// speedup vs baseline: 1.4301x; 1.2731x over previous
#include <cuda_runtime.h>
#include <cuda_fp16.h>
#include <stdint.h>
#include <math.h>

namespace fv {
constexpr int C_ = 544, CIN_ = 1088, BT_ = 1024, P4_ = 4096, P16_ = 16384, PCH_ = 34;
constexpr int KP5 = 576;

// fp32 scratch (elements)
constexpr size_t OF_F    = 0;                              // [P4][544]
constexpr size_t OF_P2   = OF_F    + (size_t)P4_*C_;       // [P4][34]
constexpr size_t OF_PP   = OF_P2   + (size_t)P4_*PCH_;     // [P4][1088]
constexpr size_t OF_AB   = OF_PP   + (size_t)P4_*CIN_;     // [P4][2176]
constexpr size_t OF_AG   = OF_AB   + (size_t)P4_*2176;     // [P16][544]
constexpr size_t OF_FST  = OF_AG   + (size_t)P16_*C_;      // [P4][1088]
constexpr size_t OF_ATTL = OF_FST  + (size_t)P4_*CIN_;
constexpr size_t OF_ATTS = OF_ATTL + (size_t)P16_;
constexpr size_t OF_SBN  = OF_ATTS + (size_t)P16_;         // [5][2][1088]
constexpr size_t OF_RSWF = OF_SBN  + (size_t)5*2*CIN_;     // 3328
constexpr size_t OF_RSW1 = OF_RSWF + 3328;
constexpr size_t OF_RSW2 = OF_RSW1 + 1152;
constexpr size_t OF_RSGA = OF_RSW2 + 1152;                 // 2176
constexpr size_t OF_RSWS = OF_RSGA + 2176;                 // 640
constexpr size_t OF_S6   = OF_RSWS + 640;                  // 2176
constexpr size_t OF_T6   = OF_S6   + 2176;
constexpr size_t OF_WT2  = OF_T6   + 2176;
constexpr size_t OF_WPT  = OF_WT2  + 2176;                 // [34][1088]
constexpr size_t TOT_F32 = OF_WPT + (size_t)PCH_*CIN_;

// fp16 row-major scratch [rows][Kpad]
constexpr size_t SZ_FB   = (size_t)P4_ * KP5;
constexpr size_t SZ_H    = (size_t)P16_ * CIN_;
constexpr size_t SZ_WF   = (size_t)3328 * KP5;   // We(2176) | W01(1088) | pad(64)
constexpr size_t SZ_WB   = (size_t)1152 * 1088;
constexpr size_t SZ_WGA  = (size_t)2176 * 1088;
constexpr size_t SZ_WS   = (size_t)640 * 1088;

constexpr size_t OB_FB   = 0;
constexpr size_t OB_H0   = OB_FB   + SZ_FB;
constexpr size_t OB_H1   = OB_H0   + SZ_H;
constexpr size_t OB_H2   = OB_H1   + SZ_H;
constexpr size_t OB_G    = OB_H2   + SZ_H;
constexpr size_t OB_WF   = OB_G    + SZ_H;
constexpr size_t OB_W1   = OB_WF   + SZ_WF;
constexpr size_t OB_W2   = OB_W1   + SZ_WB;
constexpr size_t OB_WGA  = OB_W2   + SZ_WB;
constexpr size_t OB_WS   = OB_WGA  + SZ_WGA;
constexpr size_t TOT_H16 = OB_WS   + SZ_WS;

// mega-prep block ranges (256-thread blocks)
constexpr int PB_BF   = 1152;                 // build_f
constexpr int PB_WE   = PB_BF + 272;          // wsp We (mode 3, MP 2176)
constexpr int PB_W01  = PB_WE + 144;          // wsp Wsm^T (mode 2, MP 1152)
constexpr int PB_W1   = PB_W01 + 144;
constexpr int PB_W2   = PB_W1 + 144;
constexpr int PB_WGA  = PB_W2 + 272;          // wsp ag|att (mode 5, MP 2176)
constexpr int PB_WS   = PB_WGA + 80;          // wsp ag_s (MP 640)
constexpr int PB_BN   = PB_WS + 22;           // bn_fold
constexpr int PB_BP   = PB_BN + 545;          // build_p
constexpr int PB_AI   = PB_BP + 64;           // attl_init
constexpr int PB_CM   = PB_AI + 9;            // combine
constexpr int PB_WT   = PB_CM + 145;          // wposT
constexpr int PB_TOT  = PB_WT;
}  // namespace fv

__device__ float  g_F32[fv::TOT_F32];
__device__ __half g_H16[fv::TOT_H16];

using namespace fv;

// ---------------- baseline-PTX helpers ----------------
__device__ __forceinline__ uint32_t smem_u32(const void* p) {
    uint32_t a;
    asm("{ .reg .u64 t; cvta.to.shared.u64 t, %1; cvt.u32.u64 %0, t; }" : "=r"(a) : "l"(p));
    return a;
}
__device__ __forceinline__ void cp16(uint32_t dst, const void* src) {
    asm volatile("cp.async.cg.shared.global [%0], [%1], 16;" :: "r"(dst), "l"(src));
}
#define CP_COMMIT() asm volatile("cp.async.commit_group;" ::: "memory")
#define CP_WAIT(n)  asm volatile("cp.async.wait_group %0;" :: "n"(n) : "memory")

__device__ __forceinline__ void ldsm_x4(uint32_t (&r)[4], uint32_t addr) {
    asm volatile("ldmatrix.sync.aligned.m8n8.x4.shared.b16 {%0,%1,%2,%3}, [%4];"
                 : "=r"(r[0]), "=r"(r[1]), "=r"(r[2]), "=r"(r[3]) : "r"(addr));
}
__device__ __forceinline__ void mma_f16(float (&d)[4], const uint32_t (&a)[4],
                                        const uint32_t (&b)[2]) {
    asm volatile(
        "mma.sync.aligned.m16n8k16.row.col.f32.f16.f16.f32 "
        "{%0,%1,%2,%3}, {%4,%5,%6,%7}, {%8,%9}, {%0,%1,%2,%3};"
        : "+f"(d[0]), "+f"(d[1]), "+f"(d[2]), "+f"(d[3])
        : "r"(a[0]), "r"(a[1]), "r"(a[2]), "r"(a[3]), "r"(b[0]), "r"(b[1]));
}

// weight fetch modes:
// 0: srcA[r*ld + k]
// 2: stacked Wsm^T: srcA[(r/544)*295936 + k*544 + (r%544)]
// 3: stacked We:    srcA[(r%1088)*1088 + (r/1088)*544 + k]
// 5: two stacked:   r<1088 ? srcA[r*1088+k] : srcB[(r-1088)*1088+k]
__device__ __forceinline__ float wfetch(const float* srcA, const float* srcB,
                                        int ld, int mode, int r, int k) {
    if (mode == 0) return srcA[(size_t)r * ld + k];
    if (mode == 2) return srcA[(size_t)(r / 544) * 295936 + (size_t)k * 544 + (r % 544)];
    if (mode == 3) return srcA[(size_t)(r % 1088) * 1088 + (size_t)(r / 1088) * 544 + k];
    return (r < 1088) ? srcA[(size_t)r * 1088 + k] : srcB[(size_t)(r - 1088) * 1088 + k];
}

// per-row scale + fp16 convert; one warp per row, 8 rows per block
__device__ __forceinline__ void dev_wsp(int lb, const float* srcA, const float* srcB,
                                        int ld, int Msrc, int Ksrc, int Kp, int MP, int mode,
                                        float* rs, __half* dst) {
    int wid = threadIdx.x >> 5, lane = threadIdx.x & 31;
    int r = lb * 8 + wid;
    if (r >= MP) return;
    float mx = 0.f;
    if (r < Msrc)
        for (int k = lane; k < Ksrc; k += 32)
            mx = fmaxf(mx, fabsf(wfetch(srcA, srcB, ld, mode, r, k)));
#pragma unroll
    for (int o = 16; o > 0; o >>= 1) mx = fmaxf(mx, __shfl_xor_sync(0xFFFFFFFFu, mx, o));
    int e = 0;
    if (mx > 0.f) frexpf(mx, &e);
    float rsv = exp2f((float)e);
    if (lane == 0) rs[r] = rsv;
    float inv = 1.0f / rsv;
    for (int k0 = lane * 8; k0 < Kp; k0 += 256) {
        union { __half h[8]; uint4 v; } ph;
#pragma unroll
        for (int ee = 0; ee < 8; ee++) {
            int k = k0 + ee;
            float x = (r < Msrc && k < Ksrc) ? wfetch(srcA, srcB, ld, mode, r, k) * inv : 0.f;
            ph.h[ee] = __float2half(x);
        }
        *reinterpret_cast<uint4*>(dst + (size_t)r * Kp + k0) = ph.v;
    }
}

// ---------------- mega prep kernel ----------------
__global__ void k_prep(const float* __restrict__ x, const float* __restrict__ pos2d,
                       const float* __restrict__ w_e, const float* __restrict__ Wsm,
                       const float* __restrict__ w1, const float* __restrict__ w2,
                       const float* __restrict__ w_ag, const float* __restrict__ w_att,
                       const float* __restrict__ w_ag_s,
                       const float* __restrict__ b0, const float* __restrict__ b1,
                       const float* __restrict__ b2, const float* __restrict__ b3,
                       const float* __restrict__ b4,
                       const float* __restrict__ w_att_s, const float* __restrict__ b_att_s,
                       const float* __restrict__ w_pos,
                       float* __restrict__ F, __half* __restrict__ FB,
                       float* __restrict__ P2, float* __restrict__ SBN,
                       float* __restrict__ RSWF, float* __restrict__ RSW1,
                       float* __restrict__ RSW2, float* __restrict__ RSGA,
                       float* __restrict__ RSWS,
                       __half* __restrict__ WF, __half* __restrict__ W1d,
                       __half* __restrict__ W2d, __half* __restrict__ WGA,
                       __half* __restrict__ WS,
                       float* __restrict__ S6, float* __restrict__ T6,
                       float* __restrict__ WT2, float* __restrict__ ATTL,
                       float* __restrict__ WPT) {
    int b = blockIdx.x, t = threadIdx.x;
    if (b < PB_BF) {
        int idx = b * 256 + t;
        int p = idx / 72, c0 = (idx % 72) * 8;
        int bt = p >> 2, n = p & 3;
        union { __half h[8]; uint4 v; } ph;
        float vv[8];
#pragma unroll
        for (int e = 0; e < 8; e++) {
            int c = c0 + e;
            vv[e] = (c < C_) ? x[((size_t)bt * C_ + c) * 4 + n] : 0.f;
            ph.h[e] = __float2half(vv[e]);
        }
        *reinterpret_cast<uint4*>(FB + (size_t)p * KP5 + c0) = ph.v;
        if (c0 < C_) {
            float4* d = reinterpret_cast<float4*>(F + (size_t)p * C_ + c0);
            d[0] = make_float4(vv[0], vv[1], vv[2], vv[3]);
            d[1] = make_float4(vv[4], vv[5], vv[6], vv[7]);
        }
    } else if (b < PB_WE) {
        dev_wsp(b - PB_BF, w_e, nullptr, 0, 2176, 544, KP5, 2176, 3, RSWF, WF);
    } else if (b < PB_W01) {
        dev_wsp(b - PB_WE, Wsm, nullptr, 0, 1088, 544, KP5, 1152, 2,
                RSWF + 2176, WF + (size_t)2176 * KP5);
    } else if (b < PB_W1) {
        dev_wsp(b - PB_W01, w1, nullptr, CIN_, 1088, 1088, 1088, 1152, 0, RSW1, W1d);
    } else if (b < PB_W2) {
        dev_wsp(b - PB_W1, w2, nullptr, CIN_, 1088, 1088, 1088, 1152, 0, RSW2, W2d);
    } else if (b < PB_WGA) {
        dev_wsp(b - PB_W2, w_ag, w_att, CIN_, 2176, 1088, 1088, 2176, 5, RSGA, WGA);
    } else if (b < PB_WS) {
        dev_wsp(b - PB_WGA, w_ag_s, nullptr, CIN_, 544, 1088, 1088, 640, 0, RSWS, WS);
    } else if (b < PB_BN) {
        int idx = (b - PB_WS) * 256 + t;
        if (idx < 5 * CIN_) {
            int w = idx / CIN_, c = idx % CIN_;
            const float* bn = w == 0 ? b0 : w == 1 ? b1 : w == 2 ? b2 : w == 3 ? b3 : b4;
            float s = bn[c] * rsqrtf(bn[3 * CIN_ + c] + 1e-5f);
            SBN[w * 2 * CIN_ + c] = s;
            SBN[w * 2 * CIN_ + CIN_ + c] = bn[CIN_ + c] - bn[2 * CIN_ + c] * s;
        }
    } else if (b < PB_BP) {
        int idx = (b - PB_BN) * 256 + t;
        if (idx < P4_ * PCH_) {
            int p = idx / PCH_, k = idx % PCH_;
            P2[idx] = pos2d[((size_t)(p >> 2) * PCH_ + k) * 4 + (p & 3)];
        }
    } else if (b < PB_AI) {
        int p = (b - PB_BP) * 256 + t;
        if (p < P16_) ATTL[p] = b_att_s[0];
    } else if (b < PB_CM) {
        int m = (b - PB_AI) * 256 + t;
        if (m < 2176) {
            const float* bn = (m < 1088) ? b3 : b4;
            int c = (m < 1088) ? m : m - 1088;
            float s = bn[c] * rsqrtf(bn[3 * CIN_ + c] + 1e-5f);
            S6[m] = s;
            T6[m] = bn[CIN_ + c] - bn[2 * CIN_ + c] * s;
            WT2[m] = (m < 1088) ? 0.f : w_att_s[c];
        }
    } else {
        int idx = (b - PB_CM) * 256 + t;
        if (idx < PCH_ * CIN_) {
            int k = idx / CIN_, o = idx % CIN_;
            WPT[idx] = w_pos[o * PCH_ + k];
        }
    }
}

// ---------------- remaining elementwise ----------------
__global__ void k_pos(const float* __restrict__ wpt, const float* __restrict__ P2,
                      float* __restrict__ PP) {
    int idx = blockIdx.x * blockDim.x + threadIdx.x;
    if (idx >= P4_ * CIN_) return;
    int p = idx / CIN_, o = idx % CIN_;
    float acc = 0.f;
#pragma unroll
    for (int k = 0; k < PCH_; k++) acc = fmaf(wpt[k * CIN_ + o], P2[p * PCH_ + k], acc);
    PP[idx] = acc;
}

// thread = (bt, 8-channel chunk); computes all 16 (i,j) outputs with rows in regs
__global__ void __launch_bounds__(256)
k_h0(const float* __restrict__ AB, const float* __restrict__ PP,
     const float* __restrict__ bpos, const float* __restrict__ sbn,
     __half* __restrict__ hh) {
    int idx = blockIdx.x * blockDim.x + threadIdx.x;
    if (idx >= BT_ * 136) return;
    int bt = idx / 136, o0 = (idx % 136) * 8;

    float A[4][8], Bv[4][8], Pp[4][8];
#pragma unroll
    for (int r = 0; r < 4; r++) {
        const float4* a4 = reinterpret_cast<const float4*>(AB + (size_t)(bt*4+r)*2176 + o0);
        float4 a0 = a4[0], a1 = a4[1];
        A[r][0]=a0.x; A[r][1]=a0.y; A[r][2]=a0.z; A[r][3]=a0.w;
        A[r][4]=a1.x; A[r][5]=a1.y; A[r][6]=a1.z; A[r][7]=a1.w;
        const float4* b4p = reinterpret_cast<const float4*>(AB + (size_t)(bt*4+r)*2176 + 1088 + o0);
        float4 b0 = b4p[0], b1 = b4p[1];
        Bv[r][0]=b0.x; Bv[r][1]=b0.y; Bv[r][2]=b0.z; Bv[r][3]=b0.w;
        Bv[r][4]=b1.x; Bv[r][5]=b1.y; Bv[r][6]=b1.z; Bv[r][7]=b1.w;
        const float4* p4p = reinterpret_cast<const float4*>(PP + (size_t)(bt*4+r)*CIN_ + o0);
        float4 p0 = p4p[0], p1 = p4p[1];
        Pp[r][0]=p0.x; Pp[r][1]=p0.y; Pp[r][2]=p0.z; Pp[r][3]=p0.w;
        Pp[r][4]=p1.x; Pp[r][5]=p1.y; Pp[r][6]=p1.z; Pp[r][7]=p1.w;
    }
    float s[8], t[8], bp[8];
#pragma unroll
    for (int e = 0; e < 8; e++) {
        s[e] = sbn[o0 + e];
        t[e] = sbn[CIN_ + o0 + e];
        bp[e] = bpos[o0 + e];
    }
#pragma unroll
    for (int i = 0; i < 4; i++)
#pragma unroll
        for (int j = 0; j < 4; j++) {
            union { __half h[8]; uint4 v; } ph;
#pragma unroll
            for (int e = 0; e < 8; e++) {
                float v = fmaxf(fmaf(s[e], A[i][e] + Bv[j][e], t[e]), 0.f);
                v += Pp[i][e] - Pp[j][e] + bp[e];
                ph.h[e] = __float2half(v);
            }
            *reinterpret_cast<uint4*>(hh + (size_t)(bt*16 + i*4 + j) * CIN_ + o0) = ph.v;
        }
}

__global__ void k_softmax(const float* __restrict__ L, float* __restrict__ S) {
    int r = blockIdx.x * blockDim.x + threadIdx.x;
    if (r >= P4_) return;
    float l0 = L[r*4], l1 = L[r*4+1], l2 = L[r*4+2], l3 = L[r*4+3];
    float m = fmaxf(fmaxf(l0, l1), fmaxf(l2, l3));
    float e0 = __expf(l0-m), e1 = __expf(l1-m), e2 = __expf(l2-m), e3 = __expf(l3-m);
    float inv = 1.f / (e0+e1+e2+e3);
    S[r*4]=e0*inv; S[r*4+1]=e1*inv; S[r*4+2]=e2*inv; S[r*4+3]=e3*inv;
}

__global__ void k_fuse(const float* __restrict__ F, const float* __restrict__ FST,
                       const float* __restrict__ AG, const float* __restrict__ S,
                       float* __restrict__ out) {
    int idx = blockIdx.x * blockDim.x + threadIdx.x;
    if (idx >= BT_ * 2176) return;
    int bt = idx / 2176, rem = idx % 2176;
    int i = rem / C_, d = rem % C_;
    int ri = bt * 4 + i;
    float acc = F[(size_t)ri * C_ + d];
#pragma unroll
    for (int j = 0; j < 4; j++) {
        float a = S[ri * 4 + j];
        if (j == i) acc = fmaf(FST[(size_t)ri * CIN_ + d], a, acc);
        else acc = fmaf(FST[(size_t)(bt*4+j) * CIN_ + 544 + d] *
                        AG[(size_t)(bt*16+i*4+j) * C_ + d], a, acc);
    }
    out[(size_t)bt * 2176 + d * 4 + i] = acc;
}

// ---------------- HMMA fp16 GEMM (R12 engine): 128x128 tile, 256 thr, 4x2 warps, BK=64 ----------------
// EPI: 2 relu->fp16 | 3 fp16resid+relu->fp16 | 4 v*rs+bias fp32
//      | 6 hybrid: m<1088 relu->fp16 G, m>=1088 att-dot atomicAdd
//      | 7 dual fp32: m<2176 -> outf (ld 2176), 2176<=m<3264 -> outf2 (ld 1088), else skip
constexpr int TIL = 16384;       // 128 rows x 128 B
constexpr int STG = 2 * TIL;     // 32 KB
constexpr int SMEMB = 98304;     // 3 stages (Cs 128x132 f32 aliases)

__device__ __forceinline__ uint32_t swadr(uint32_t base, int row, int c16) {
    return base + row * 128 + ((c16 ^ (row & 7)) << 4);
}

template <int EPI>
__global__ void __launch_bounds__(256, 2)
gemm_mma(const __half* __restrict__ Ag, const __half* __restrict__ Bg,
         int K, int KB, int Mreal,
         float* __restrict__ outf, int ldo,
         __half* __restrict__ oh, int ldob,
         const float* __restrict__ sv, const float* __restrict__ tv,
         const float* __restrict__ rs,
         const __half* __restrict__ r16,
         const float* __restrict__ watt,
         float* __restrict__ outf2) {
    extern __shared__ __half smbuf[];
    const uint32_t sb = smem_u32(smbuf);
    const int tid = threadIdx.x, lane = tid & 31, wid = tid >> 5;
    const int mt = blockIdx.x, nt = blockIdx.y;
    const int wm = (wid & 3) * 32, wn = (wid >> 2) * 64;

    float acc[2][8][4];
#pragma unroll
    for (int a = 0; a < 2; a++)
#pragma unroll
        for (int b = 0; b < 8; b++)
#pragma unroll
            for (int c = 0; c < 4; c++) acc[a][b][c] = 0.f;

    auto load_stage = [&](int s, int kb) {
        uint32_t dstb = sb + s * STG;
        int k0 = kb * 64;
#pragma unroll
        for (int c = 0; c < 4; c++) {
            int q = tid + c * 256;
            int r = q >> 3, ch = q & 7;
            uint32_t d = dstb + r * 128 + ((ch ^ (r & 7)) << 4);
            size_t offA = (size_t)(mt * 128 + r) * K + k0 + ch * 8;
            size_t offB = (size_t)(nt * 128 + r) * K + k0 + ch * 8;
            cp16(d,       Ag + offA);
            cp16(d + TIL, Bg + offB);
        }
    };

    const int grp = lane >> 3, lrow = lane & 7;

    auto compute_stage = [&](int s) {
        uint32_t base = sb + s * STG;
#pragma unroll
        for (int ks2 = 0; ks2 < 4; ks2++) {
            uint32_t ah[2][4], bf[8][2];
            const int cA = ks2 * 2 + (grp >> 1);
            const int cB = ks2 * 2 + (grp & 1);
#pragma unroll
            for (int mi = 0; mi < 2; mi++) {
                int row = wm + mi * 16 + (grp & 1) * 8 + lrow;
                ldsm_x4(ah[mi], swadr(base, row, cA));
            }
#pragma unroll
            for (int n2 = 0; n2 < 4; n2++) {
                int row = wn + n2 * 16 + (grp >> 1) * 8 + lrow;
                uint32_t q[4];
                ldsm_x4(q, swadr(base + TIL, row, cB));
                bf[n2 * 2][0] = q[0]; bf[n2 * 2][1] = q[1];
                bf[n2 * 2 + 1][0] = q[2]; bf[n2 * 2 + 1][1] = q[3];
            }
#pragma unroll
            for (int mi = 0; mi < 2; mi++)
#pragma unroll
                for (int ni = 0; ni < 8; ni++) mma_f16(acc[mi][ni], ah[mi], bf[ni]);
        }
    };

    load_stage(0, 0); CP_COMMIT();
    if (KB > 1) { load_stage(1, 1); CP_COMMIT(); }
    for (int kb = 0; kb < KB; kb++) {
        if (kb + 1 < KB) { CP_WAIT(1); } else { CP_WAIT(0); }
        __syncthreads();
        if (kb + 2 < KB) { load_stage((kb + 2) % 3, kb + 2); CP_COMMIT(); }
        compute_stage(kb % 3);
    }
    __syncthreads();

    float* Cs = reinterpret_cast<float*>(smbuf);
#pragma unroll
    for (int mi = 0; mi < 2; mi++)
#pragma unroll
        for (int ni = 0; ni < 8; ni++) {
            int rm = wm + mi * 16 + (lane >> 2);
            int cn = wn + ni * 8 + 2 * (lane & 3);
            Cs[cn * 132 + rm]           = acc[mi][ni][0];
            Cs[(cn + 1) * 132 + rm]     = acc[mi][ni][1];
            Cs[cn * 132 + rm + 8]       = acc[mi][ni][2];
            Cs[(cn + 1) * 132 + rm + 8] = acc[mi][ni][3];
        }
    __syncthreads();

    {
        int nl = tid >> 1, m0 = (tid & 1) * 64;
        int ng = nt * 128 + nl;
        int mg0 = mt * 128 + m0;
        if constexpr (EPI == 6) {
            if (mg0 < 1088) {
#pragma unroll
                for (int j0 = 0; j0 < 64; j0 += 8) {
                    union { __half h[8]; uint4 v; } ph;
#pragma unroll
                    for (int e = 0; e < 8; e++) {
                        int m = mg0 + j0 + e;
                        float v = Cs[nl * 132 + m0 + j0 + e] * rs[m];
                        ph.h[e] = __float2half(fmaxf(fmaf(sv[m], v, tv[m]), 0.f));
                    }
                    *reinterpret_cast<uint4*>(oh + (size_t)ng * ldob + mg0 + j0) = ph.v;
                }
            } else {
                float wsum = 0.f;
#pragma unroll 8
                for (int j = 0; j < 64; j++) {
                    int m = mg0 + j;
                    float v = Cs[nl * 132 + m0 + j] * rs[m];
                    wsum = fmaf(fmaxf(fmaf(sv[m], v, tv[m]), 0.f), watt[m], wsum);
                }
                atomicAdd(&outf[ng], wsum);
            }
        } else if constexpr (EPI == 7) {
#pragma unroll
            for (int j0 = 0; j0 < 64; j0 += 4) {
                int m = mg0 + j0;
                if (m >= 3264) break;   // skip W01 padding rows
                float4 ov;
                float* pv = reinterpret_cast<float*>(&ov);
#pragma unroll
                for (int e = 0; e < 4; e++)
                    pv[e] = Cs[nl * 132 + m0 + j0 + e] * rs[m + e];
                if (m < 2176)
                    *reinterpret_cast<float4*>(outf + (size_t)ng * 2176 + m) = ov;
                else
                    *reinterpret_cast<float4*>(outf2 + (size_t)ng * 1088 + m - 2176) = ov;
            }
        } else if constexpr (EPI == 2 || EPI == 3) {
#pragma unroll
            for (int j0 = 0; j0 < 64; j0 += 8) {
                if (mg0 + j0 >= Mreal) break;
                union { __half h[8]; uint4 v; } ph;
                float rv[8];
                if constexpr (EPI == 3) {
                    uint4 r4 = *reinterpret_cast<const uint4*>(r16 + (size_t)ng * ldob + mg0 + j0);
                    const __half* rr = reinterpret_cast<const __half*>(&r4);
#pragma unroll
                    for (int e = 0; e < 8; e++) rv[e] = __half2float(rr[e]);
                }
#pragma unroll
                for (int e = 0; e < 8; e++) {
                    int m = mg0 + j0 + e;
                    float v = Cs[nl * 132 + m0 + j0 + e] * rs[m];
                    float w = fmaxf(fmaf(sv[m], v, tv[m]), 0.f);
                    if constexpr (EPI == 3) w += rv[e];
                    ph.h[e] = __float2half(w);
                }
                *reinterpret_cast<uint4*>(oh + (size_t)ng * ldob + mg0 + j0) = ph.v;
            }
        } else {  // EPI 4
#pragma unroll
            for (int j0 = 0; j0 < 64; j0 += 4) {
                if (mg0 + j0 >= Mreal) break;
                float4 ov;
                float* pv = reinterpret_cast<float*>(&ov);
#pragma unroll
                for (int e = 0; e < 4; e++) {
                    int m = mg0 + j0 + e;
                    pv[e] = Cs[nl * 132 + m0 + j0 + e] * rs[m] + sv[m];
                }
                *reinterpret_cast<float4*>(outf + (size_t)ng * ldo + mg0 + j0) = ov;
            }
        }
    }
}

// ---------------- launch ----------------
extern "C" void kernel_launch(void* const* d_in, const int* in_sizes, int n_in,
                              void* d_out, int out_size) {
    const float *x = (const float*)d_in[0], *pos2d = (const float*)d_in[1];
    const float *w_pos = (const float*)d_in[2], *b_pos = (const float*)d_in[3];
    const float *w_e = (const float*)d_in[4],  *w1 = (const float*)d_in[6];
    const float *w2 = (const float*)d_in[8],   *w_ag = (const float*)d_in[10];
    const float *w_ag_s = (const float*)d_in[12], *b_ag_s = (const float*)d_in[13];
    const float *w_att = (const float*)d_in[14], *w_att_s = (const float*)d_in[16];
    const float *b_att_s = (const float*)d_in[17], *Wsm = (const float*)d_in[18];
    float* out = (float*)d_out;

    float* F32 = nullptr;  __half* H16 = nullptr;
    cudaGetSymbolAddress((void**)&F32, g_F32);
    cudaGetSymbolAddress((void**)&H16, g_H16);

    float *F = F32+OF_F, *P2 = F32+OF_P2, *PP = F32+OF_PP;
    float *AB = F32+OF_AB, *AG = F32+OF_AG, *FST = F32+OF_FST;
    float *ATTL = F32+OF_ATTL, *ATTS = F32+OF_ATTS, *SBN = F32+OF_SBN;
    float *RSWF = F32+OF_RSWF, *RSW1 = F32+OF_RSW1, *RSW2 = F32+OF_RSW2;
    float *RSGA = F32+OF_RSGA, *RSWS = F32+OF_RSWS;
    float *S6 = F32+OF_S6, *T6 = F32+OF_T6, *WT2 = F32+OF_WT2, *WPT = F32+OF_WPT;

    cudaFuncSetAttribute(gemm_mma<2>, cudaFuncAttributeMaxDynamicSharedMemorySize, SMEMB);
    cudaFuncSetAttribute(gemm_mma<3>, cudaFuncAttributeMaxDynamicSharedMemorySize, SMEMB);
    cudaFuncSetAttribute(gemm_mma<4>, cudaFuncAttributeMaxDynamicSharedMemorySize, SMEMB);
    cudaFuncSetAttribute(gemm_mma<6>, cudaFuncAttributeMaxDynamicSharedMemorySize, SMEMB);
    cudaFuncSetAttribute(gemm_mma<7>, cudaFuncAttributeMaxDynamicSharedMemorySize, SMEMB);

    // 1: mega prep (everything input-only)
    k_prep<<<PB_TOT, 256>>>(x, pos2d, w_e, Wsm, w1, w2, w_ag, w_att, w_ag_s,
                            (const float*)d_in[5], (const float*)d_in[7],
                            (const float*)d_in[9], (const float*)d_in[11],
                            (const float*)d_in[15], w_att_s, b_att_s, w_pos,
                            F, H16+OB_FB, P2, SBN, RSWF, RSW1, RSW2, RSGA, RSWS,
                            H16+OB_WF, H16+OB_W1, H16+OB_W2, H16+OB_WGA, H16+OB_WS,
                            S6, T6, WT2, ATTL, WPT);

    // 2: stacked [We(2176); W01(1088)] @ f -> AB | FST
    gemm_mma<7><<<dim3(26,32),256,SMEMB>>>(H16+OB_WF, H16+OB_FB,
                                           KP5, 9, 3328, AB, 2176, nullptr, 0,
                                           nullptr, nullptr, RSWF, nullptr, nullptr, FST);
    // 3-4: pos emb + h0 assembly (register-blocked)
    k_pos<<<(P4_*CIN_+255)/256, 256>>>(WPT, P2, PP);
    k_h0<<<(BT_*136+255)/256, 256>>>(AB, PP, b_pos, SBN, H16+OB_H0);

    // 5-6: trunk
    gemm_mma<2><<<dim3(9,128),256,SMEMB>>>(H16+OB_W1, H16+OB_H0,
                                           1088, 17, 1088, nullptr, 0, H16+OB_H1, CIN_,
                                           SBN+2*CIN_, SBN+3*CIN_, RSW1, nullptr, nullptr, nullptr);
    gemm_mma<3><<<dim3(9,128),256,SMEMB>>>(H16+OB_W2, H16+OB_H1,
                                           1088, 17, 1088, nullptr, 0, H16+OB_H2, CIN_,
                                           SBN+4*CIN_, SBN+5*CIN_, RSW2, H16+OB_H0, nullptr, nullptr);
    // 7: merged ag+att stacked GEMM (hybrid epilogue; ATTL pre-seeded in prep)
    gemm_mma<6><<<dim3(17,128),256,SMEMB>>>(H16+OB_WGA, H16+OB_H2,
                                            1088, 17, 2176, ATTL, 0, H16+OB_G, CIN_,
                                            S6, T6, RSGA, nullptr, WT2, nullptr);
    // 8: ag_s
    gemm_mma<4><<<dim3(5,128),256,SMEMB>>>(H16+OB_WS, H16+OB_G,
                                           1088, 17, 544, AG, C_, nullptr, 0,
                                           b_ag_s, nullptr, RSWS, nullptr, nullptr, nullptr);
    // 9-10: softmax + fuse
    k_softmax<<<(P4_+255)/256, 256>>>(ATTL, ATTS);
    k_fuse<<<(BT_*2176+255)/256, 256>>>(F, FST, AG, ATTS, out);
}

// round 17
// speedup vs baseline: 1.5793x; 1.1043x over previous
#include <cuda_runtime.h>
#include <cuda_fp16.h>
#include <stdint.h>
#include <math.h>

namespace fv {
constexpr int C_ = 544, CIN_ = 1088, BT_ = 1024, P4_ = 4096, P16_ = 16384, PCH_ = 34;
constexpr int KP5 = 576;

// fp32 scratch (elements)
constexpr size_t OF_F    = 0;                              // [P4][544]
constexpr size_t OF_P2   = OF_F    + (size_t)P4_*C_;       // [P4][34]
constexpr size_t OF_AB   = OF_P2   + (size_t)P4_*PCH_;     // [P4][2176]
constexpr size_t OF_AG   = OF_AB   + (size_t)P4_*2176;     // [P16][544]
constexpr size_t OF_FST  = OF_AG   + (size_t)P16_*C_;      // [P4][1088]
constexpr size_t OF_ATTL = OF_FST  + (size_t)P4_*CIN_;
constexpr size_t OF_ATTS = OF_ATTL + (size_t)P16_;
constexpr size_t OF_SBN  = OF_ATTS + (size_t)P16_;         // [5][2][1088]
constexpr size_t OF_S6   = OF_SBN  + (size_t)5*2*CIN_;     // 2176
constexpr size_t OF_T6   = OF_S6   + 2176;
constexpr size_t OF_WT2  = OF_T6   + 2176;
constexpr size_t OF_WPT  = OF_WT2  + 2176;                 // [34][1088]
constexpr size_t TOT_F32 = OF_WPT + (size_t)PCH_*CIN_;

// fp16 row-major scratch [rows][Kpad]
constexpr size_t SZ_FB   = (size_t)P4_ * KP5;
constexpr size_t SZ_H    = (size_t)P16_ * CIN_;
constexpr size_t SZ_WF   = (size_t)3328 * KP5;   // We(2176) | W01(1088) | pad(64)
constexpr size_t SZ_WB   = (size_t)1152 * 1088;
constexpr size_t SZ_WGA  = (size_t)2176 * 1088;
constexpr size_t SZ_WS   = (size_t)640 * 1088;

constexpr size_t OB_FB   = 0;
constexpr size_t OB_H0   = OB_FB   + SZ_FB;
constexpr size_t OB_H1   = OB_H0   + SZ_H;
constexpr size_t OB_H2   = OB_H1   + SZ_H;
constexpr size_t OB_G    = OB_H2   + SZ_H;
constexpr size_t OB_WF   = OB_G    + SZ_H;
constexpr size_t OB_W1   = OB_WF   + SZ_WF;
constexpr size_t OB_W2   = OB_W1   + SZ_WB;
constexpr size_t OB_WGA  = OB_W2   + SZ_WB;
constexpr size_t OB_WS   = OB_WGA  + SZ_WGA;
constexpr size_t TOT_H16 = OB_WS   + SZ_WS;

// mega-prep block ranges (256-thread blocks)
constexpr int PB_BF   = 1152;                 // build_f
constexpr int PB_WE   = PB_BF + 272;          // wconv We (mode 3, MP 2176)
constexpr int PB_W01  = PB_WE + 144;          // wconv Wsm^T (mode 2, MP 1152)
constexpr int PB_W1   = PB_W01 + 144;
constexpr int PB_W2   = PB_W1 + 144;
constexpr int PB_WGA  = PB_W2 + 272;          // wconv ag|att (mode 5, MP 2176)
constexpr int PB_WS   = PB_WGA + 80;          // wconv ag_s (MP 640)
constexpr int PB_BN   = PB_WS + 22;           // bn_fold
constexpr int PB_BP   = PB_BN + 545;          // build_p
constexpr int PB_AI   = PB_BP + 64;           // attl_init
constexpr int PB_CM   = PB_AI + 9;            // combine
constexpr int PB_WT   = PB_CM + 145;          // wposT
constexpr int PB_TOT  = PB_WT;
}  // namespace fv

__device__ float  g_F32[fv::TOT_F32];
__device__ __half g_H16[fv::TOT_H16];

using namespace fv;

// ---------------- baseline-PTX helpers ----------------
__device__ __forceinline__ uint32_t smem_u32(const void* p) {
    uint32_t a;
    asm("{ .reg .u64 t; cvta.to.shared.u64 t, %1; cvt.u32.u64 %0, t; }" : "=r"(a) : "l"(p));
    return a;
}
__device__ __forceinline__ void cp16(uint32_t dst, const void* src) {
    asm volatile("cp.async.cg.shared.global [%0], [%1], 16;" :: "r"(dst), "l"(src));
}
#define CP_COMMIT() asm volatile("cp.async.commit_group;" ::: "memory")
#define CP_WAIT(n)  asm volatile("cp.async.wait_group %0;" :: "n"(n) : "memory")

__device__ __forceinline__ void ldsm_x4(uint32_t (&r)[4], uint32_t addr) {
    asm volatile("ldmatrix.sync.aligned.m8n8.x4.shared.b16 {%0,%1,%2,%3}, [%4];"
                 : "=r"(r[0]), "=r"(r[1]), "=r"(r[2]), "=r"(r[3]) : "r"(addr));
}
__device__ __forceinline__ void mma_f16(float (&d)[4], const uint32_t (&a)[4],
                                        const uint32_t (&b)[2]) {
    asm volatile(
        "mma.sync.aligned.m16n8k16.row.col.f32.f16.f16.f32 "
        "{%0,%1,%2,%3}, {%4,%5,%6,%7}, {%8,%9}, {%0,%1,%2,%3};"
        : "+f"(d[0]), "+f"(d[1]), "+f"(d[2]), "+f"(d[3])
        : "r"(a[0]), "r"(a[1]), "r"(a[2]), "r"(a[3]), "r"(b[0]), "r"(b[1]));
}

// weight fetch modes:
// 0: srcA[r*ld + k]
// 2: stacked Wsm^T: srcA[(r/544)*295936 + k*544 + (r%544)]
// 3: stacked We:    srcA[(r%1088)*1088 + (r/1088)*544 + k]
// 5: two stacked:   r<1088 ? srcA[r*1088+k] : srcB[(r-1088)*1088+k]
__device__ __forceinline__ float wfetch(const float* srcA, const float* srcB,
                                        int ld, int mode, int r, int k) {
    if (mode == 0) return srcA[(size_t)r * ld + k];
    if (mode == 2) return srcA[(size_t)(r / 544) * 295936 + (size_t)k * 544 + (r % 544)];
    if (mode == 3) return srcA[(size_t)(r % 1088) * 1088 + (size_t)(r / 1088) * 544 + k];
    return (r < 1088) ? srcA[(size_t)r * 1088 + k] : srcB[(size_t)(r - 1088) * 1088 + k];
}

// single-pass fp16 convert; one warp per row, 8 rows per block
__device__ __forceinline__ void dev_wconv(int lb, const float* srcA, const float* srcB,
                                          int ld, int Msrc, int Ksrc, int Kp, int MP, int mode,
                                          __half* dst) {
    int wid = threadIdx.x >> 5, lane = threadIdx.x & 31;
    int r = lb * 8 + wid;
    if (r >= MP) return;
    for (int k0 = lane * 8; k0 < Kp; k0 += 256) {
        union { __half h[8]; uint4 v; } ph;
#pragma unroll
        for (int ee = 0; ee < 8; ee++) {
            int k = k0 + ee;
            float x = (r < Msrc && k < Ksrc) ? wfetch(srcA, srcB, ld, mode, r, k) : 0.f;
            ph.h[ee] = __float2half(x);
        }
        *reinterpret_cast<uint4*>(dst + (size_t)r * Kp + k0) = ph.v;
    }
}

// ---------------- mega prep kernel ----------------
__global__ void k_prep(const float* __restrict__ x, const float* __restrict__ pos2d,
                       const float* __restrict__ w_e, const float* __restrict__ Wsm,
                       const float* __restrict__ w1, const float* __restrict__ w2,
                       const float* __restrict__ w_ag, const float* __restrict__ w_att,
                       const float* __restrict__ w_ag_s,
                       const float* __restrict__ b0, const float* __restrict__ b1,
                       const float* __restrict__ b2, const float* __restrict__ b3,
                       const float* __restrict__ b4,
                       const float* __restrict__ w_att_s, const float* __restrict__ b_att_s,
                       const float* __restrict__ w_pos,
                       float* __restrict__ F, __half* __restrict__ FB,
                       float* __restrict__ P2, float* __restrict__ SBN,
                       __half* __restrict__ WF, __half* __restrict__ W1d,
                       __half* __restrict__ W2d, __half* __restrict__ WGA,
                       __half* __restrict__ WS,
                       float* __restrict__ S6, float* __restrict__ T6,
                       float* __restrict__ WT2, float* __restrict__ ATTL,
                       float* __restrict__ WPT) {
    int b = blockIdx.x, t = threadIdx.x;
    if (b < PB_BF) {
        int idx = b * 256 + t;
        int p = idx / 72, c0 = (idx % 72) * 8;
        int bt = p >> 2, n = p & 3;
        union { __half h[8]; uint4 v; } ph;
        float vv[8];
#pragma unroll
        for (int e = 0; e < 8; e++) {
            int c = c0 + e;
            vv[e] = (c < C_) ? x[((size_t)bt * C_ + c) * 4 + n] : 0.f;
            ph.h[e] = __float2half(vv[e]);
        }
        *reinterpret_cast<uint4*>(FB + (size_t)p * KP5 + c0) = ph.v;
        if (c0 < C_) {
            float4* d = reinterpret_cast<float4*>(F + (size_t)p * C_ + c0);
            d[0] = make_float4(vv[0], vv[1], vv[2], vv[3]);
            d[1] = make_float4(vv[4], vv[5], vv[6], vv[7]);
        }
    } else if (b < PB_WE) {
        dev_wconv(b - PB_BF, w_e, nullptr, 0, 2176, 544, KP5, 2176, 3, WF);
    } else if (b < PB_W01) {
        dev_wconv(b - PB_WE, Wsm, nullptr, 0, 1088, 544, KP5, 1152, 2,
                  WF + (size_t)2176 * KP5);
    } else if (b < PB_W1) {
        dev_wconv(b - PB_W01, w1, nullptr, CIN_, 1088, 1088, 1088, 1152, 0, W1d);
    } else if (b < PB_W2) {
        dev_wconv(b - PB_W1, w2, nullptr, CIN_, 1088, 1088, 1088, 1152, 0, W2d);
    } else if (b < PB_WGA) {
        dev_wconv(b - PB_W2, w_ag, w_att, CIN_, 2176, 1088, 1088, 2176, 5, WGA);
    } else if (b < PB_WS) {
        dev_wconv(b - PB_WGA, w_ag_s, nullptr, CIN_, 544, 1088, 1088, 640, 0, WS);
    } else if (b < PB_BN) {
        int idx = (b - PB_WS) * 256 + t;
        if (idx < 5 * CIN_) {
            int w = idx / CIN_, c = idx % CIN_;
            const float* bn = w == 0 ? b0 : w == 1 ? b1 : w == 2 ? b2 : w == 3 ? b3 : b4;
            float s = bn[c] * rsqrtf(bn[3 * CIN_ + c] + 1e-5f);
            SBN[w * 2 * CIN_ + c] = s;
            SBN[w * 2 * CIN_ + CIN_ + c] = bn[CIN_ + c] - bn[2 * CIN_ + c] * s;
        }
    } else if (b < PB_BP) {
        int idx = (b - PB_BN) * 256 + t;
        if (idx < P4_ * PCH_) {
            int p = idx / PCH_, k = idx % PCH_;
            P2[idx] = pos2d[((size_t)(p >> 2) * PCH_ + k) * 4 + (p & 3)];
        }
    } else if (b < PB_AI) {
        int p = (b - PB_BP) * 256 + t;
        if (p < P16_) ATTL[p] = b_att_s[0];
    } else if (b < PB_CM) {
        int m = (b - PB_AI) * 256 + t;
        if (m < 2176) {
            const float* bn = (m < 1088) ? b3 : b4;
            int c = (m < 1088) ? m : m - 1088;
            float s = bn[c] * rsqrtf(bn[3 * CIN_ + c] + 1e-5f);
            S6[m] = s;
            T6[m] = bn[CIN_ + c] - bn[2 * CIN_ + c] * s;
            WT2[m] = (m < 1088) ? 0.f : w_att_s[c];
        }
    } else {
        int idx = (b - PB_CM) * 256 + t;
        if (idx < PCH_ * CIN_) {
            int k = idx / CIN_, o = idx % CIN_;
            WPT[idx] = w_pos[o * PCH_ + k];
        }
    }
}

// ---------------- h0 assembly with fused pos-embedding GEMV ----------------
// thread = (bt, 8-channel chunk); computes all 16 (i,j) outputs, PP on the fly
__global__ void __launch_bounds__(256)
k_h0(const float* __restrict__ AB, const float* __restrict__ P2,
     const float* __restrict__ WPT, const float* __restrict__ bpos,
     const float* __restrict__ sbn, __half* __restrict__ hh) {
    int idx = blockIdx.x * blockDim.x + threadIdx.x;
    if (idx >= BT_ * 136) return;
    int bt = idx / 136, o0 = (idx % 136) * 8;

    // PP[r][e] = sum_k WPT[k][o0+e] * P2[bt*4+r][k]
    float Pp[4][8];
#pragma unroll
    for (int r = 0; r < 4; r++)
#pragma unroll
        for (int e = 0; e < 8; e++) Pp[r][e] = 0.f;
#pragma unroll 2
    for (int k = 0; k < PCH_; k++) {
        const float4* w4 = reinterpret_cast<const float4*>(WPT + (size_t)k * CIN_ + o0);
        float4 w0 = w4[0], w1v = w4[1];
        float wk[8] = {w0.x, w0.y, w0.z, w0.w, w1v.x, w1v.y, w1v.z, w1v.w};
#pragma unroll
        for (int r = 0; r < 4; r++) {
            float pv = P2[(size_t)(bt * 4 + r) * PCH_ + k];
#pragma unroll
            for (int e = 0; e < 8; e++) Pp[r][e] = fmaf(wk[e], pv, Pp[r][e]);
        }
    }

    float A[4][8], Bv[4][8];
#pragma unroll
    for (int r = 0; r < 4; r++) {
        const float4* a4 = reinterpret_cast<const float4*>(AB + (size_t)(bt*4+r)*2176 + o0);
        float4 a0 = a4[0], a1 = a4[1];
        A[r][0]=a0.x; A[r][1]=a0.y; A[r][2]=a0.z; A[r][3]=a0.w;
        A[r][4]=a1.x; A[r][5]=a1.y; A[r][6]=a1.z; A[r][7]=a1.w;
        const float4* b4p = reinterpret_cast<const float4*>(AB + (size_t)(bt*4+r)*2176 + 1088 + o0);
        float4 b0 = b4p[0], b1 = b4p[1];
        Bv[r][0]=b0.x; Bv[r][1]=b0.y; Bv[r][2]=b0.z; Bv[r][3]=b0.w;
        Bv[r][4]=b1.x; Bv[r][5]=b1.y; Bv[r][6]=b1.z; Bv[r][7]=b1.w;
    }
    float s[8], t[8], bp[8];
#pragma unroll
    for (int e = 0; e < 8; e++) {
        s[e] = sbn[o0 + e];
        t[e] = sbn[CIN_ + o0 + e];
        bp[e] = bpos[o0 + e];
    }
#pragma unroll
    for (int i = 0; i < 4; i++)
#pragma unroll
        for (int j = 0; j < 4; j++) {
            union { __half h[8]; uint4 v; } ph;
#pragma unroll
            for (int e = 0; e < 8; e++) {
                float v = fmaxf(fmaf(s[e], A[i][e] + Bv[j][e], t[e]), 0.f);
                v += Pp[i][e] - Pp[j][e] + bp[e];
                ph.h[e] = __float2half(v);
            }
            *reinterpret_cast<uint4*>(hh + (size_t)(bt*16 + i*4 + j) * CIN_ + o0) = ph.v;
        }
}

__global__ void k_softmax(const float* __restrict__ L, float* __restrict__ S) {
    int r = blockIdx.x * blockDim.x + threadIdx.x;
    if (r >= P4_) return;
    float l0 = L[r*4], l1 = L[r*4+1], l2 = L[r*4+2], l3 = L[r*4+3];
    float m = fmaxf(fmaxf(l0, l1), fmaxf(l2, l3));
    float e0 = __expf(l0-m), e1 = __expf(l1-m), e2 = __expf(l2-m), e3 = __expf(l3-m);
    float inv = 1.f / (e0+e1+e2+e3);
    S[r*4]=e0*inv; S[r*4+1]=e1*inv; S[r*4+2]=e2*inv; S[r*4+3]=e3*inv;
}

__global__ void k_fuse(const float* __restrict__ F, const float* __restrict__ FST,
                       const float* __restrict__ AG, const float* __restrict__ S,
                       float* __restrict__ out) {
    int idx = blockIdx.x * blockDim.x + threadIdx.x;
    if (idx >= BT_ * 2176) return;
    int bt = idx / 2176, rem = idx % 2176;
    int i = rem / C_, d = rem % C_;
    int ri = bt * 4 + i;
    float acc = F[(size_t)ri * C_ + d];
#pragma unroll
    for (int j = 0; j < 4; j++) {
        float a = S[ri * 4 + j];
        if (j == i) acc = fmaf(FST[(size_t)ri * CIN_ + d], a, acc);
        else acc = fmaf(FST[(size_t)(bt*4+j) * CIN_ + 544 + d] *
                        AG[(size_t)(bt*16+i*4+j) * C_ + d], a, acc);
    }
    out[(size_t)bt * 2176 + d * 4 + i] = acc;
}

// ---------------- HMMA fp16 GEMM (R12 engine): 128x128 tile, 256 thr, 4x2 warps, BK=64 ----------------
// EPI: 2 relu->fp16 | 3 fp16resid+relu->fp16 | 4 v+bias fp32
//      | 6 hybrid: m<1088 relu->fp16 G, m>=1088 att-dot atomicAdd
//      | 7 dual fp32: m<2176 -> outf (ld 2176), 2176<=m<3264 -> outf2 (ld 1088), else skip
constexpr int TIL = 16384;       // 128 rows x 128 B
constexpr int STG = 2 * TIL;     // 32 KB
constexpr int SMEMB = 98304;     // 3 stages (Cs 128x132 f32 aliases)

__device__ __forceinline__ uint32_t swadr(uint32_t base, int row, int c16) {
    return base + row * 128 + ((c16 ^ (row & 7)) << 4);
}

template <int EPI>
__global__ void __launch_bounds__(256, 2)
gemm_mma(const __half* __restrict__ Ag, const __half* __restrict__ Bg,
         int K, int KB, int Mreal,
         float* __restrict__ outf, int ldo,
         __half* __restrict__ oh, int ldob,
         const float* __restrict__ sv, const float* __restrict__ tv,
         const __half* __restrict__ r16,
         const float* __restrict__ watt,
         float* __restrict__ outf2) {
    extern __shared__ __half smbuf[];
    const uint32_t sb = smem_u32(smbuf);
    const int tid = threadIdx.x, lane = tid & 31, wid = tid >> 5;
    const int mt = blockIdx.x, nt = blockIdx.y;
    const int wm = (wid & 3) * 32, wn = (wid >> 2) * 64;

    float acc[2][8][4];
#pragma unroll
    for (int a = 0; a < 2; a++)
#pragma unroll
        for (int b = 0; b < 8; b++)
#pragma unroll
            for (int c = 0; c < 4; c++) acc[a][b][c] = 0.f;

    auto load_stage = [&](int s, int kb) {
        uint32_t dstb = sb + s * STG;
        int k0 = kb * 64;
#pragma unroll
        for (int c = 0; c < 4; c++) {
            int q = tid + c * 256;
            int r = q >> 3, ch = q & 7;
            uint32_t d = dstb + r * 128 + ((ch ^ (r & 7)) << 4);
            size_t offA = (size_t)(mt * 128 + r) * K + k0 + ch * 8;
            size_t offB = (size_t)(nt * 128 + r) * K + k0 + ch * 8;
            cp16(d,       Ag + offA);
            cp16(d + TIL, Bg + offB);
        }
    };

    const int grp = lane >> 3, lrow = lane & 7;

    auto compute_stage = [&](int s) {
        uint32_t base = sb + s * STG;
#pragma unroll
        for (int ks2 = 0; ks2 < 4; ks2++) {
            uint32_t ah[2][4], bf[8][2];
            const int cA = ks2 * 2 + (grp >> 1);
            const int cB = ks2 * 2 + (grp & 1);
#pragma unroll
            for (int mi = 0; mi < 2; mi++) {
                int row = wm + mi * 16 + (grp & 1) * 8 + lrow;
                ldsm_x4(ah[mi], swadr(base, row, cA));
            }
#pragma unroll
            for (int n2 = 0; n2 < 4; n2++) {
                int row = wn + n2 * 16 + (grp >> 1) * 8 + lrow;
                uint32_t q[4];
                ldsm_x4(q, swadr(base + TIL, row, cB));
                bf[n2 * 2][0] = q[0]; bf[n2 * 2][1] = q[1];
                bf[n2 * 2 + 1][0] = q[2]; bf[n2 * 2 + 1][1] = q[3];
            }
#pragma unroll
            for (int mi = 0; mi < 2; mi++)
#pragma unroll
                for (int ni = 0; ni < 8; ni++) mma_f16(acc[mi][ni], ah[mi], bf[ni]);
        }
    };

    load_stage(0, 0); CP_COMMIT();
    if (KB > 1) { load_stage(1, 1); CP_COMMIT(); }
    for (int kb = 0; kb < KB; kb++) {
        if (kb + 1 < KB) { CP_WAIT(1); } else { CP_WAIT(0); }
        __syncthreads();
        if (kb + 2 < KB) { load_stage((kb + 2) % 3, kb + 2); CP_COMMIT(); }
        compute_stage(kb % 3);
    }
    __syncthreads();

    float* Cs = reinterpret_cast<float*>(smbuf);
#pragma unroll
    for (int mi = 0; mi < 2; mi++)
#pragma unroll
        for (int ni = 0; ni < 8; ni++) {
            int rm = wm + mi * 16 + (lane >> 2);
            int cn = wn + ni * 8 + 2 * (lane & 3);
            Cs[cn * 132 + rm]           = acc[mi][ni][0];
            Cs[(cn + 1) * 132 + rm]     = acc[mi][ni][1];
            Cs[cn * 132 + rm + 8]       = acc[mi][ni][2];
            Cs[(cn + 1) * 132 + rm + 8] = acc[mi][ni][3];
        }
    __syncthreads();

    {
        int nl = tid >> 1, m0 = (tid & 1) * 64;
        int ng = nt * 128 + nl;
        int mg0 = mt * 128 + m0;
        if constexpr (EPI == 6) {
            if (mg0 < 1088) {
#pragma unroll
                for (int j0 = 0; j0 < 64; j0 += 8) {
                    union { __half h[8]; uint4 v; } ph;
#pragma unroll
                    for (int e = 0; e < 8; e++) {
                        int m = mg0 + j0 + e;
                        float v = Cs[nl * 132 + m0 + j0 + e];
                        ph.h[e] = __float2half(fmaxf(fmaf(sv[m], v, tv[m]), 0.f));
                    }
                    *reinterpret_cast<uint4*>(oh + (size_t)ng * ldob + mg0 + j0) = ph.v;
                }
            } else {
                float wsum = 0.f;
#pragma unroll 8
                for (int j = 0; j < 64; j++) {
                    int m = mg0 + j;
                    float v = Cs[nl * 132 + m0 + j];
                    wsum = fmaf(fmaxf(fmaf(sv[m], v, tv[m]), 0.f), watt[m], wsum);
                }
                atomicAdd(&outf[ng], wsum);
            }
        } else if constexpr (EPI == 7) {
#pragma unroll
            for (int j0 = 0; j0 < 64; j0 += 4) {
                int m = mg0 + j0;
                if (m >= 3264) break;   // skip W01 padding rows
                float4 ov;
                float* pv = reinterpret_cast<float*>(&ov);
#pragma unroll
                for (int e = 0; e < 4; e++)
                    pv[e] = Cs[nl * 132 + m0 + j0 + e];
                if (m < 2176)
                    *reinterpret_cast<float4*>(outf + (size_t)ng * 2176 + m) = ov;
                else
                    *reinterpret_cast<float4*>(outf2 + (size_t)ng * 1088 + m - 2176) = ov;
            }
        } else if constexpr (EPI == 2 || EPI == 3) {
#pragma unroll
            for (int j0 = 0; j0 < 64; j0 += 8) {
                if (mg0 + j0 >= Mreal) break;
                union { __half h[8]; uint4 v; } ph;
                float rv[8];
                if constexpr (EPI == 3) {
                    uint4 r4 = *reinterpret_cast<const uint4*>(r16 + (size_t)ng * ldob + mg0 + j0);
                    const __half* rr = reinterpret_cast<const __half*>(&r4);
#pragma unroll
                    for (int e = 0; e < 8; e++) rv[e] = __half2float(rr[e]);
                }
#pragma unroll
                for (int e = 0; e < 8; e++) {
                    int m = mg0 + j0 + e;
                    float v = Cs[nl * 132 + m0 + j0 + e];
                    float w = fmaxf(fmaf(sv[m], v, tv[m]), 0.f);
                    if constexpr (EPI == 3) w += rv[e];
                    ph.h[e] = __float2half(w);
                }
                *reinterpret_cast<uint4*>(oh + (size_t)ng * ldob + mg0 + j0) = ph.v;
            }
        } else {  // EPI 4
#pragma unroll
            for (int j0 = 0; j0 < 64; j0 += 4) {
                if (mg0 + j0 >= Mreal) break;
                float4 ov;
                float* pv = reinterpret_cast<float*>(&ov);
#pragma unroll
                for (int e = 0; e < 4; e++) {
                    int m = mg0 + j0 + e;
                    pv[e] = Cs[nl * 132 + m0 + j0 + e] + sv[m];
                }
                *reinterpret_cast<float4*>(outf + (size_t)ng * ldo + mg0 + j0) = ov;
            }
        }
    }
}

// ---------------- launch ----------------
extern "C" void kernel_launch(void* const* d_in, const int* in_sizes, int n_in,
                              void* d_out, int out_size) {
    const float *x = (const float*)d_in[0], *pos2d = (const float*)d_in[1];
    const float *w_pos = (const float*)d_in[2], *b_pos = (const float*)d_in[3];
    const float *w_e = (const float*)d_in[4],  *w1 = (const float*)d_in[6];
    const float *w2 = (const float*)d_in[8],   *w_ag = (const float*)d_in[10];
    const float *w_ag_s = (const float*)d_in[12], *b_ag_s = (const float*)d_in[13];
    const float *w_att = (const float*)d_in[14], *w_att_s = (const float*)d_in[16];
    const float *b_att_s = (const float*)d_in[17], *Wsm = (const float*)d_in[18];
    float* out = (float*)d_out;

    float* F32 = nullptr;  __half* H16 = nullptr;
    cudaGetSymbolAddress((void**)&F32, g_F32);
    cudaGetSymbolAddress((void**)&H16, g_H16);

    float *F = F32+OF_F, *P2 = F32+OF_P2;
    float *AB = F32+OF_AB, *AG = F32+OF_AG, *FST = F32+OF_FST;
    float *ATTL = F32+OF_ATTL, *ATTS = F32+OF_ATTS, *SBN = F32+OF_SBN;
    float *S6 = F32+OF_S6, *T6 = F32+OF_T6, *WT2 = F32+OF_WT2, *WPT = F32+OF_WPT;

    cudaFuncSetAttribute(gemm_mma<2>, cudaFuncAttributeMaxDynamicSharedMemorySize, SMEMB);
    cudaFuncSetAttribute(gemm_mma<3>, cudaFuncAttributeMaxDynamicSharedMemorySize, SMEMB);
    cudaFuncSetAttribute(gemm_mma<4>, cudaFuncAttributeMaxDynamicSharedMemorySize, SMEMB);
    cudaFuncSetAttribute(gemm_mma<6>, cudaFuncAttributeMaxDynamicSharedMemorySize, SMEMB);
    cudaFuncSetAttribute(gemm_mma<7>, cudaFuncAttributeMaxDynamicSharedMemorySize, SMEMB);

    // 1: mega prep
    k_prep<<<PB_TOT, 256>>>(x, pos2d, w_e, Wsm, w1, w2, w_ag, w_att, w_ag_s,
                            (const float*)d_in[5], (const float*)d_in[7],
                            (const float*)d_in[9], (const float*)d_in[11],
                            (const float*)d_in[15], w_att_s, b_att_s, w_pos,
                            F, H16+OB_FB, P2, SBN,
                            H16+OB_WF, H16+OB_W1, H16+OB_W2, H16+OB_WGA, H16+OB_WS,
                            S6, T6, WT2, ATTL, WPT);

    // 2: stacked [We(2176); W01(1088)] @ f -> AB | FST
    gemm_mma<7><<<dim3(26,32),256,SMEMB>>>(H16+OB_WF, H16+OB_FB,
                                           KP5, 9, 3328, AB, 2176, nullptr, 0,
                                           nullptr, nullptr, nullptr, nullptr, FST);
    // 3: h0 assembly (pos-embedding fused)
    k_h0<<<(BT_*136+255)/256, 256>>>(AB, P2, WPT, b_pos, SBN, H16+OB_H0);

    // 4-5: trunk (slot 4 profiled)
    gemm_mma<2><<<dim3(9,128),256,SMEMB>>>(H16+OB_W1, H16+OB_H0,
                                           1088, 17, 1088, nullptr, 0, H16+OB_H1, CIN_,
                                           SBN+2*CIN_, SBN+3*CIN_, nullptr, nullptr, nullptr);
    gemm_mma<3><<<dim3(9,128),256,SMEMB>>>(H16+OB_W2, H16+OB_H1,
                                           1088, 17, 1088, nullptr, 0, H16+OB_H2, CIN_,
                                           SBN+4*CIN_, SBN+5*CIN_, H16+OB_H0, nullptr, nullptr);
    // 6: merged ag+att stacked GEMM (hybrid epilogue; ATTL pre-seeded in prep)
    gemm_mma<6><<<dim3(17,128),256,SMEMB>>>(H16+OB_WGA, H16+OB_H2,
                                            1088, 17, 2176, ATTL, 0, H16+OB_G, CIN_,
                                            S6, T6, nullptr, WT2, nullptr);
    // 7: ag_s
    gemm_mma<4><<<dim3(5,128),256,SMEMB>>>(H16+OB_WS, H16+OB_G,
                                           1088, 17, 544, AG, C_, nullptr, 0,
                                           b_ag_s, nullptr, nullptr, nullptr, nullptr);
    // 8-9: softmax + fuse
    k_softmax<<<(P4_+255)/256, 256>>>(ATTL, ATTS);
    k_fuse<<<(BT_*2176+255)/256, 256>>>(F, FST, AG, ATTS, out);
}